// round 10
// baseline (speedup 1.0000x reference)
#include <cuda_runtime.h>
#include <cuda_bf16.h>
#include <math.h>
#include <stdint.h>

// LSTM: B=64, T=512, I=H=1024. Output: h_T [64,1024] then c_T [64,1024] (fp32).
#define Bsz  64
#define Tlen 512
#define Idim 1024
#define Hdim 1024
#define G4   4096
#define KP   3072   // 3*1024 hi/lo-split K

// ---------------- scratch ----------------
// g_xg: [cta 128][t 512][row 64][32 cols(unit*4+gate)], gates f,i,g,o
__device__ __align__(16) float         g_xg[(size_t)Tlen * Bsz * G4];
__device__ __align__(16) __nv_bfloat16 g_xbf[(size_t)Tlen * Bsz * KP]; // [m][3072] A'=[x_hi|x_lo|x_hi]
__device__ __align__(16) __nv_bfloat16 g_Wbp[(size_t)G4 * KP];          // [n][3072] B'=[W_hi|W_hi|W_lo]
__device__ __align__(16) float         g_bsum[G4];
// h' double buf, MMA A-fragment layout: [buf 2][kt 128 (0-63 hi,64-127 lo)][mt 4][lane 32][reg 4] u32
__device__ __align__(16) uint32_t      g_hF[2 * 128 * 4 * 32 * 4];
__device__ unsigned g_bar_cnt;
__device__ unsigned g_bar_gen;

// ---------------- helpers ----------------
__device__ __forceinline__ uint32_t smem_to_u32(const void* p) {
    uint32_t a;
    asm("{ .reg .u64 t; cvta.to.shared.u64 t, %1; cvt.u32.u64 %0, t; }" : "=r"(a) : "l"(p));
    return a;
}
__device__ __forceinline__ void ldsm_x4(uint32_t& r0, uint32_t& r1, uint32_t& r2, uint32_t& r3,
                                        uint32_t addr) {
    asm volatile("ldmatrix.sync.aligned.m8n8.x4.shared.b16 {%0,%1,%2,%3}, [%4];"
                 : "=r"(r0), "=r"(r1), "=r"(r2), "=r"(r3) : "r"(addr));
}
__device__ __forceinline__ void mma16816(float* c, const uint32_t* a, uint32_t b0, uint32_t b1) {
    asm volatile(
        "mma.sync.aligned.m16n8k16.row.col.f32.bf16.bf16.f32 "
        "{%0,%1,%2,%3}, {%4,%5,%6,%7}, {%8,%9}, {%0,%1,%2,%3};"
        : "+f"(c[0]), "+f"(c[1]), "+f"(c[2]), "+f"(c[3])
        : "r"(a[0]), "r"(a[1]), "r"(a[2]), "r"(a[3]), "r"(b0), "r"(b1));
}
__device__ __forceinline__ float sigf(float x) { return 1.f / (1.f + __expf(-x)); }
#define CP_ASYNC16(dst, src) \
    asm volatile("cp.async.cg.shared.global [%0], [%1], 16;" :: "r"(dst), "l"(src) : "memory")
#define CP_COMMIT() asm volatile("cp.async.commit_group;" ::: "memory")
#define CP_WAIT(n)  asm volatile("cp.async.wait_group %0;" :: "n"(n) : "memory")

// ---------------- packW ----------------
__global__ __launch_bounds__(256) void packW_kernel(
    const float* __restrict__ Wif, const float* __restrict__ Wii,
    const float* __restrict__ Wig, const float* __restrict__ Wio)
{
    __shared__ float ts[64][65];
    const int tid = threadIdx.x;
    const int k0 = blockIdx.x * 64, h0 = blockIdx.y * 64, gate = blockIdx.z;
    const float* W = (gate == 0) ? Wif : (gate == 1) ? Wii : (gate == 2) ? Wig : Wio;
#pragma unroll
    for (int q = 0; q < 16; ++q) {
        int i = tid + q * 256;
        int r = i >> 6, c = i & 63;
        ts[r][c] = W[(size_t)(k0 + r) * Hdim + h0 + c];
    }
    __syncthreads();
#pragma unroll
    for (int q = 0; q < 16; ++q) {
        int i = tid + q * 256;
        int h = i >> 6, kk = i & 63;
        float v = ts[kk][h];
        __nv_bfloat16 hi = __float2bfloat16(v);
        __nv_bfloat16 lo = __float2bfloat16(v - __bfloat162float(hi));
        size_t base = (size_t)(gate * 1024 + h0 + h) * KP + k0 + kk;
        g_Wbp[base]        = hi;
        g_Wbp[base + 1024] = hi;
        g_Wbp[base + 2048] = lo;
    }
}
__global__ void bias_kernel(const float* __restrict__ bif_, const float* __restrict__ bhf,
                            const float* __restrict__ bii_, const float* __restrict__ bhi,
                            const float* __restrict__ big_, const float* __restrict__ bhg,
                            const float* __restrict__ bio_, const float* __restrict__ bho)
{
    int idx = blockIdx.x * blockDim.x + threadIdx.x;
    if (idx >= G4) return;
    int gate = idx >> 10, hid = idx & 1023;
    const float* bx = (gate == 0) ? bif_ : (gate == 1) ? bii_ : (gate == 2) ? big_ : bio_;
    const float* bh = (gate == 0) ? bhf  : (gate == 1) ? bhi  : (gate == 2) ? bhg  : bho;
    g_bsum[idx] = bx[hid] + bh[hid];
}

// ---------------- xconv ----------------
__global__ __launch_bounds__(256) void xconv_kernel(const float* __restrict__ x)
{
    const int m = blockIdx.x;
    const int b = m & 63, t = m >> 6;
    const float4* __restrict__ xr = (const float4*)(x + (size_t)(b * Tlen + t) * Idim);
    uint32_t* __restrict__ dst = (uint32_t*)(g_xbf + (size_t)m * KP);
    const int j = threadIdx.x;
    float4 v = xr[j];
    __nv_bfloat16 h0 = __float2bfloat16(v.x), h1 = __float2bfloat16(v.y);
    __nv_bfloat16 h2 = __float2bfloat16(v.z), h3 = __float2bfloat16(v.w);
    __nv_bfloat16 l0 = __float2bfloat16(v.x - __bfloat162float(h0));
    __nv_bfloat16 l1 = __float2bfloat16(v.y - __bfloat162float(h1));
    __nv_bfloat16 l2 = __float2bfloat16(v.z - __bfloat162float(h2));
    __nv_bfloat16 l3 = __float2bfloat16(v.w - __bfloat162float(h3));
    uint32_t hp0 = (uint32_t)__bfloat16_as_ushort(h0) | ((uint32_t)__bfloat16_as_ushort(h1) << 16);
    uint32_t hp1 = (uint32_t)__bfloat16_as_ushort(h2) | ((uint32_t)__bfloat16_as_ushort(h3) << 16);
    uint32_t lp0 = (uint32_t)__bfloat16_as_ushort(l0) | ((uint32_t)__bfloat16_as_ushort(l1) << 16);
    uint32_t lp1 = (uint32_t)__bfloat16_as_ushort(l2) | ((uint32_t)__bfloat16_as_ushort(l3) << 16);
    dst[j * 2]        = hp0; dst[j * 2 + 1]        = hp1;
    dst[512 + j * 2]  = lp0; dst[512 + j * 2 + 1]  = lp1;
    dst[1024 + j * 2] = hp0; dst[1024 + j * 2 + 1] = hp1;
}

// ---------------- HMMA input projection ----------------
#define PBK   32
#define PNCH  (KP / PBK)   // 96
#define SROW  40

__global__ __launch_bounds__(256, 2) void proj_mma_kernel()
{
    __shared__ __align__(16) __nv_bfloat16 sA[2][128 * SROW];
    __shared__ __align__(16) __nv_bfloat16 sB[2][128 * SROW];

    const int tid = threadIdx.x, lane = tid & 31, wid = tid >> 5;
    const int bn0 = blockIdx.x * 128, bm0 = blockIdx.y * 128;
    const int wm = wid >> 2, wn = wid & 3;

    const uint32_t sAb = smem_to_u32(sA);
    const uint32_t sBb = smem_to_u32(sB);
    const int rowoff = ((lane >> 3) & 1) * 8 + (lane & 7);
    const int kkoff  = (lane >> 4) * 8;
    const int lrow = tid >> 2, lj = tid & 3;

    float acc[4][4][4];
#pragma unroll
    for (int i = 0; i < 4; ++i)
#pragma unroll
        for (int j = 0; j < 4; ++j)
#pragma unroll
            for (int r = 0; r < 4; ++r) acc[i][j][r] = 0.f;

#pragma unroll
    for (int q = 0; q < 2; ++q) {
        int row = lrow + q * 64;
        CP_ASYNC16(sAb + row * 80 + lj * 16, g_xbf + (size_t)(bm0 + row) * KP + lj * 8);
        CP_ASYNC16(sBb + row * 80 + lj * 16, g_Wbp + (size_t)(bn0 + row) * KP + lj * 8);
    }
    CP_COMMIT();

    int buf = 0;
    for (int ch = 0; ch < PNCH; ++ch) {
        if (ch + 1 < PNCH) {
            const int kb = (ch + 1) * PBK;
            const uint32_t da = sAb + (buf ^ 1) * (128 * SROW * 2);
            const uint32_t db = sBb + (buf ^ 1) * (128 * SROW * 2);
#pragma unroll
            for (int q = 0; q < 2; ++q) {
                int row = lrow + q * 64;
                CP_ASYNC16(da + row * 80 + lj * 16, g_xbf + (size_t)(bm0 + row) * KP + kb + lj * 8);
                CP_ASYNC16(db + row * 80 + lj * 16, g_Wbp + (size_t)(bn0 + row) * KP + kb + lj * 8);
            }
            CP_COMMIT();
            CP_WAIT(1);
        } else {
            CP_WAIT(0);
        }
        __syncthreads();
        const uint32_t aBase = sAb + buf * (128 * SROW * 2);
        const uint32_t bBase = sBb + buf * (128 * SROW * 2);
#pragma unroll
        for (int k0 = 0; k0 < PBK; k0 += 16) {
            uint32_t af[4][4], bfr[2][4];
#pragma unroll
            for (int mt = 0; mt < 4; ++mt)
                ldsm_x4(af[mt][0], af[mt][1], af[mt][2], af[mt][3],
                        aBase + (uint32_t)(((wm * 64 + mt * 16 + rowoff) * SROW + k0 + kkoff) * 2));
#pragma unroll
            for (int pt = 0; pt < 2; ++pt)
                ldsm_x4(bfr[pt][0], bfr[pt][1], bfr[pt][2], bfr[pt][3],
                        bBase + (uint32_t)(((wn * 32 + pt * 16 + rowoff) * SROW + k0 + kkoff) * 2));
#pragma unroll
            for (int mt = 0; mt < 4; ++mt)
#pragma unroll
                for (int nt = 0; nt < 4; ++nt) {
                    int pt = nt >> 1, hi = nt & 1;
                    mma16816(acc[mt][nt], af[mt], bfr[pt][hi], bfr[pt][hi + 2]);
                }
        }
        __syncthreads();
        buf ^= 1;
    }

    // epilogue -> xg [cta 128][t][row 64][32 cols(u*4+gate)], bias folded
    const int erow = lane >> 2, ecol = (lane & 3) * 2;
#pragma unroll
    for (int mt = 0; mt < 4; ++mt)
#pragma unroll
        for (int nt = 0; nt < 4; ++nt) {
            int r = bm0 + wm * 64 + mt * 16 + erow;     // m = t*64 + b
            int c = bn0 + wn * 32 + nt * 8 + ecol;
            int tt = r >> 6, b = r & 63;
            int gate = c >> 10, hid = c & 1023, cta = hid >> 3, u = hid & 7;
            size_t base = (size_t)cta * (512 * 64 * 32) + (size_t)tt * 2048 + b * 32 + u * 4 + gate;
            float b0 = g_bsum[c], b1 = g_bsum[c + 1];
            g_xg[base]           = acc[mt][nt][0] + b0;
            g_xg[base + 4]       = acc[mt][nt][1] + b1;   // unit u+1
            g_xg[base + 256]     = acc[mt][nt][2] + b0;   // row b+8
            g_xg[base + 256 + 4] = acc[mt][nt][3] + b1;
        }
}

// ---------------- grid barrier ----------------
__device__ __forceinline__ void grid_sync(unsigned nb)
{
    __threadfence();
    __syncthreads();
    if (threadIdx.x == 0) {
        unsigned gen = *(volatile unsigned*)&g_bar_gen;
        unsigned arr = atomicAdd(&g_bar_cnt, 1);
        if (arr == nb - 1) {
            g_bar_cnt = 0;
            __threadfence();
            *(volatile unsigned*)&g_bar_gen = gen + 1;
        } else {
            while (*(volatile unsigned*)&g_bar_gen == gen) { __nanosleep(32); }
        }
    }
    __syncthreads();
}

// ---------------- HMMA persistent recurrence: 128 CTAs x 512 thr, 32 cols, hi-reuse ----------------
// CTA owns 8 units x 4 gates (col = u*4+gate). K split 4 ways over warps (kh = wid>>2),
// each warp: 16 hi phys tiles (A loaded once -> W_hi AND W_lo sections) + 16 lo tiles.
#define BPITCH 3080
#define REC_BS   (32 * BPITCH * 2)          // 197120
#define REC_SMEM (REC_BS + 4 * 64 * 32 * 4) // +32768 = 229888

__global__ __launch_bounds__(512, 1) void lstm_rec_mma(
    const float* __restrict__ Whf, const float* __restrict__ Whi,
    const float* __restrict__ Whg, const float* __restrict__ Who,
    float* __restrict__ out)
{
    extern __shared__ __align__(16) char smr[];
    __nv_bfloat16* Bs = (__nv_bfloat16*)smr;
    float* red = (float*)(smr + REC_BS);     // [kh 4][row 64][col 32]

    const int tid = threadIdx.x, lane = tid & 31, wid = tid >> 5;
    const int cta = blockIdx.x;              // 0..127
    const int mt = wid & 3, kh = wid >> 2;   // SMSP = mt, 4 kh warps per SMSP
    const unsigned NB = gridDim.x;

    // fill Wh' slice (col = u*4+gate): sec0,1 = hi, sec2 = lo
    for (int idx = tid; idx < 32 * 1024; idx += 512) {
        int c = idx & 31, k = idx >> 5;
        int u = c >> 2, gate = c & 3;
        const float* W = (gate == 0) ? Whf : (gate == 1) ? Whi : (gate == 2) ? Whg : Who;
        float v = W[(size_t)k * Hdim + cta * 8 + u];
        __nv_bfloat16 hi = __float2bfloat16(v);
        __nv_bfloat16 lo = __float2bfloat16(v - __bfloat162float(hi));
        Bs[c * BPITCH + k]        = hi;
        Bs[c * BPITCH + 1024 + k] = hi;
        Bs[c * BPITCH + 2048 + k] = lo;
    }
    // zero h buf0: 65536 u32 over 128*512 threads
    g_hF[cta * 512 + tid] = 0u;
    grid_sync(NB);

    const uint32_t Bbase = smem_to_u32(Bs);
    const int rowoff = ((lane >> 3) & 1) * 8 + (lane & 7);
    const int kkoff  = (lane >> 4) * 8;
    const int erow   = lane >> 2;
    const int uu     = (lane & 3) * 2;
    // cell identity: one thread per (row, unit)
    const int crow = tid >> 3, cu = tid & 7;
    const int K    = cta * 8 + cu;
    const size_t ctaSlab = (size_t)cta * (512 * 64 * 32);
    const int pmt = crow >> 4, prr = crow & 15;
    const int c16 = K & 15;
    const int plane = (prr & 7) * 4 + ((c16 >> 1) & 3);
    const int preg  = (prr >> 3) + 2 * (c16 >> 3);
    const int phalf = K & 1;
    const int ktHi = K >> 4, ktLo = 64 + (K >> 4);
    float cst = 0.f;

    for (int t = 0; t < Tlen; ++t) {
        const uint32_t* __restrict__ hF = g_hF + (size_t)(t & 1) * 65536;
        float4 xv = *(const float4*)(g_xg + ctaSlab + (size_t)t * 2048 + crow * 32 + cu * 4);

        float acc[4][4];
#pragma unroll
        for (int i = 0; i < 4; ++i)
#pragma unroll
            for (int j = 0; j < 4; ++j) acc[i][j] = 0.f;

        // hi phys tiles: A loaded once, used for W_hi (kp=kt*16) and W_lo (kp=2048+kt*16)
#pragma unroll 2
        for (int s = 0; s < 16; ++s) {
            const int kt = kh * 16 + s;
            uint4 av4 = *(const uint4*)(hF + ((kt * 4 + mt) * 32 + lane) * 4);
            uint32_t av[4] = {av4.x, av4.y, av4.z, av4.w};
#pragma unroll
            for (int sec = 0; sec < 2; ++sec) {
                const int kp = kt * 16 + sec * 2048;
#pragma unroll
                for (int pt = 0; pt < 2; ++pt) {
                    uint32_t bb[4];
                    ldsm_x4(bb[0], bb[1], bb[2], bb[3],
                            Bbase + (uint32_t)(((pt * 16 + rowoff) * BPITCH + kp + kkoff) * 2));
                    mma16816(acc[pt * 2 + 0], av, bb[0], bb[2]);
                    mma16816(acc[pt * 2 + 1], av, bb[1], bb[3]);
                }
            }
        }
        // lo phys tiles: kp = kt*16 (1024..2047 = W_hi second copy)
#pragma unroll 2
        for (int s = 0; s < 16; ++s) {
            const int kt = 64 + kh * 16 + s;
            uint4 av4 = *(const uint4*)(hF + ((kt * 4 + mt) * 32 + lane) * 4);
            uint32_t av[4] = {av4.x, av4.y, av4.z, av4.w};
            const int kp = kt * 16;
#pragma unroll
            for (int pt = 0; pt < 2; ++pt) {
                uint32_t bb[4];
                ldsm_x4(bb[0], bb[1], bb[2], bb[3],
                        Bbase + (uint32_t)(((pt * 16 + rowoff) * BPITCH + kp + kkoff) * 2));
                mma16816(acc[pt * 2 + 0], av, bb[0], bb[2]);
                mma16816(acc[pt * 2 + 1], av, bb[1], bb[3]);
            }
        }

        // write partials: red[kh][row][col]
#pragma unroll
        for (int nt = 0; nt < 4; ++nt) {
            int base = (kh * 64 + mt * 16 + erow) * 32 + nt * 8 + uu;
            *(float2*)&red[base]       = make_float2(acc[nt][0], acc[nt][1]);
            *(float2*)&red[base + 256] = make_float2(acc[nt][2], acc[nt][3]);  // row +8
        }
        __syncthreads();
        // cell phase: 512 threads, one (row, unit) each; gate quad contiguous
        {
            const float4* r4 = (const float4*)red;
            float4 s0 = r4[(0 * 64 + crow) * 8 + cu];
            float4 s1 = r4[(1 * 64 + crow) * 8 + cu];
            float4 s2 = r4[(2 * 64 + crow) * 8 + cu];
            float4 s3 = r4[(3 * 64 + crow) * 8 + cu];
            float pf = s0.x + s1.x + s2.x + s3.x + xv.x;
            float pi = s0.y + s1.y + s2.y + s3.y + xv.y;
            float pg = s0.z + s1.z + s2.z + s3.z + xv.z;
            float po = s0.w + s1.w + s2.w + s3.w + xv.w;
            float f  = sigf(pf);
            float ii = sigf(pi);
            float gg = tanhf(pg);
            float oo = sigf(po);
            float cn = f * cst + ii * gg;
            cst = cn;
            float hn = tanhf(cn) * oo;
            __nv_bfloat16 hi = __float2bfloat16(hn);
            __nv_bfloat16 lo = __float2bfloat16(hn - __bfloat162float(hi));
            __nv_bfloat16* hw = (__nv_bfloat16*)(g_hF + (size_t)((t + 1) & 1) * 65536);
            hw[(((ktHi * 4 + pmt) * 32 + plane) * 4 + preg) * 2 + phalf] = hi;
            hw[(((ktLo * 4 + pmt) * 32 + plane) * 4 + preg) * 2 + phalf] = lo;
            if (t == Tlen - 1) {
                out[crow * 1024 + K]         = hn;
                out[65536 + crow * 1024 + K] = cn;
            }
        }
        grid_sync(NB);
    }
}

// ---------------- launch ----------------
extern "C" void kernel_launch(void* const* d_in, const int* in_sizes, int n_in,
                              void* d_out, int out_size)
{
    // metadata order = setup_inputs() dict order:
    // 0:x, 1:W_ii, 2:W_hi, 3:W_if, 4:W_hf, 5:W_ig, 6:W_hg, 7:W_io, 8:W_ho,
    // 9:b_ii, 10:b_hi, 11:b_if, 12:b_hf, 13:b_ig, 14:b_hg, 15:b_io, 16:b_ho
    const float* x   = (const float*)d_in[0];
    const float* Wii = (const float*)d_in[1];
    const float* Whi = (const float*)d_in[2];
    const float* Wif = (const float*)d_in[3];
    const float* Whf = (const float*)d_in[4];
    const float* Wig = (const float*)d_in[5];
    const float* Whg = (const float*)d_in[6];
    const float* Wio = (const float*)d_in[7];
    const float* Who = (const float*)d_in[8];
    const float* bii = (const float*)d_in[9];
    const float* bhi = (const float*)d_in[10];
    const float* bif = (const float*)d_in[11];
    const float* bhf = (const float*)d_in[12];
    const float* big = (const float*)d_in[13];
    const float* bhg = (const float*)d_in[14];
    const float* bio = (const float*)d_in[15];
    const float* bho = (const float*)d_in[16];
    float* out = (float*)d_out;

    packW_kernel<<<dim3(16, 16, 4), 256>>>(Wif, Wii, Wig, Wio);
    bias_kernel<<<16, 256>>>(bif, bhf, bii, bhi, big, bhg, bio, bho);
    xconv_kernel<<<Tlen * Bsz, 256>>>(x);
    proj_mma_kernel<<<dim3(G4 / 128, (Tlen * Bsz) / 128), 256>>>();
    cudaFuncSetAttribute(lstm_rec_mma, cudaFuncAttributeMaxDynamicSharedMemorySize, REC_SMEM);
    lstm_rec_mma<<<128, 512, REC_SMEM>>>(Whf, Whi, Whg, Who, out);
}

// round 11
// speedup vs baseline: 1.5321x; 1.5321x over previous
#include <cuda_runtime.h>
#include <cuda_bf16.h>
#include <math.h>
#include <stdint.h>

// LSTM: B=64, T=512, I=H=1024. Output: h_T [64,1024] then c_T [64,1024] (fp32).
#define Bsz  64
#define Tlen 512
#define Idim 1024
#define Hdim 1024
#define G4   4096
#define KP   3072   // 3*1024 hi/lo-split K

// ---------------- scratch ----------------
// g_xg: [cta 256][t 512][row 64][16 cols(unit*4+gate)], gates f,i,g,o
__device__ __align__(16) float         g_xg[(size_t)Tlen * Bsz * G4];
__device__ __align__(16) __nv_bfloat16 g_xbf[(size_t)Tlen * Bsz * KP]; // [m][3072] A'=[x_hi|x_lo|x_hi]
__device__ __align__(16) __nv_bfloat16 g_Wbp[(size_t)G4 * KP];          // [n][3072] B'=[W_hi|W_hi|W_lo]
__device__ __align__(16) float         g_bsum[G4];
// h' double buf, MMA A-fragment layout: [buf 2][kt 128 (0-63 hi,64-127 lo)][mt 4][lane 32][reg 4] u32
__device__ __align__(16) uint32_t      g_hF[2 * 128 * 4 * 32 * 4];
__device__ unsigned g_bar_cnt;
__device__ unsigned g_bar_gen;

// ---------------- helpers ----------------
__device__ __forceinline__ uint32_t smem_to_u32(const void* p) {
    uint32_t a;
    asm("{ .reg .u64 t; cvta.to.shared.u64 t, %1; cvt.u32.u64 %0, t; }" : "=r"(a) : "l"(p));
    return a;
}
__device__ __forceinline__ void ldsm_x4(uint32_t& r0, uint32_t& r1, uint32_t& r2, uint32_t& r3,
                                        uint32_t addr) {
    asm volatile("ldmatrix.sync.aligned.m8n8.x4.shared.b16 {%0,%1,%2,%3}, [%4];"
                 : "=r"(r0), "=r"(r1), "=r"(r2), "=r"(r3) : "r"(addr));
}
__device__ __forceinline__ void mma16816(float* c, const uint32_t* a, uint32_t b0, uint32_t b1) {
    asm volatile(
        "mma.sync.aligned.m16n8k16.row.col.f32.bf16.bf16.f32 "
        "{%0,%1,%2,%3}, {%4,%5,%6,%7}, {%8,%9}, {%0,%1,%2,%3};"
        : "+f"(c[0]), "+f"(c[1]), "+f"(c[2]), "+f"(c[3])
        : "r"(a[0]), "r"(a[1]), "r"(a[2]), "r"(a[3]), "r"(b0), "r"(b1));
}
__device__ __forceinline__ float sigf(float x) { return 1.f / (1.f + __expf(-x)); }
#define CP_ASYNC16(dst, src) \
    asm volatile("cp.async.cg.shared.global [%0], [%1], 16;" :: "r"(dst), "l"(src) : "memory")
#define CP_COMMIT() asm volatile("cp.async.commit_group;" ::: "memory")
#define CP_WAIT(n)  asm volatile("cp.async.wait_group %0;" :: "n"(n) : "memory")

// ---------------- packW ----------------
__global__ __launch_bounds__(256) void packW_kernel(
    const float* __restrict__ Wif, const float* __restrict__ Wii,
    const float* __restrict__ Wig, const float* __restrict__ Wio)
{
    __shared__ float ts[64][65];
    const int tid = threadIdx.x;
    const int k0 = blockIdx.x * 64, h0 = blockIdx.y * 64, gate = blockIdx.z;
    const float* W = (gate == 0) ? Wif : (gate == 1) ? Wii : (gate == 2) ? Wig : Wio;
#pragma unroll
    for (int q = 0; q < 16; ++q) {
        int i = tid + q * 256;
        int r = i >> 6, c = i & 63;
        ts[r][c] = W[(size_t)(k0 + r) * Hdim + h0 + c];
    }
    __syncthreads();
#pragma unroll
    for (int q = 0; q < 16; ++q) {
        int i = tid + q * 256;
        int h = i >> 6, kk = i & 63;
        float v = ts[kk][h];
        __nv_bfloat16 hi = __float2bfloat16(v);
        __nv_bfloat16 lo = __float2bfloat16(v - __bfloat162float(hi));
        size_t base = (size_t)(gate * 1024 + h0 + h) * KP + k0 + kk;
        g_Wbp[base]        = hi;
        g_Wbp[base + 1024] = hi;
        g_Wbp[base + 2048] = lo;
    }
}
__global__ void bias_kernel(const float* __restrict__ bif_, const float* __restrict__ bhf,
                            const float* __restrict__ bii_, const float* __restrict__ bhi,
                            const float* __restrict__ big_, const float* __restrict__ bhg,
                            const float* __restrict__ bio_, const float* __restrict__ bho)
{
    int idx = blockIdx.x * blockDim.x + threadIdx.x;
    if (idx >= G4) return;
    int gate = idx >> 10, hid = idx & 1023;
    const float* bx = (gate == 0) ? bif_ : (gate == 1) ? bii_ : (gate == 2) ? big_ : bio_;
    const float* bh = (gate == 0) ? bhf  : (gate == 1) ? bhi  : (gate == 2) ? bhg  : bho;
    g_bsum[idx] = bx[hid] + bh[hid];
}

// ---------------- xconv ----------------
__global__ __launch_bounds__(256) void xconv_kernel(const float* __restrict__ x)
{
    const int m = blockIdx.x;
    const int b = m & 63, t = m >> 6;
    const float4* __restrict__ xr = (const float4*)(x + (size_t)(b * Tlen + t) * Idim);
    uint32_t* __restrict__ dst = (uint32_t*)(g_xbf + (size_t)m * KP);
    const int j = threadIdx.x;
    float4 v = xr[j];
    __nv_bfloat16 h0 = __float2bfloat16(v.x), h1 = __float2bfloat16(v.y);
    __nv_bfloat16 h2 = __float2bfloat16(v.z), h3 = __float2bfloat16(v.w);
    __nv_bfloat16 l0 = __float2bfloat16(v.x - __bfloat162float(h0));
    __nv_bfloat16 l1 = __float2bfloat16(v.y - __bfloat162float(h1));
    __nv_bfloat16 l2 = __float2bfloat16(v.z - __bfloat162float(h2));
    __nv_bfloat16 l3 = __float2bfloat16(v.w - __bfloat162float(h3));
    uint32_t hp0 = (uint32_t)__bfloat16_as_ushort(h0) | ((uint32_t)__bfloat16_as_ushort(h1) << 16);
    uint32_t hp1 = (uint32_t)__bfloat16_as_ushort(h2) | ((uint32_t)__bfloat16_as_ushort(h3) << 16);
    uint32_t lp0 = (uint32_t)__bfloat16_as_ushort(l0) | ((uint32_t)__bfloat16_as_ushort(l1) << 16);
    uint32_t lp1 = (uint32_t)__bfloat16_as_ushort(l2) | ((uint32_t)__bfloat16_as_ushort(l3) << 16);
    dst[j * 2]        = hp0; dst[j * 2 + 1]        = hp1;
    dst[512 + j * 2]  = lp0; dst[512 + j * 2 + 1]  = lp1;
    dst[1024 + j * 2] = hp0; dst[1024 + j * 2 + 1] = hp1;
}

// ---------------- HMMA input projection (R8 version) ----------------
#define PBK   32
#define PNCH  (KP / PBK)   // 96
#define SROW  40

__global__ __launch_bounds__(256, 2) void proj_mma_kernel()
{
    __shared__ __align__(16) __nv_bfloat16 sA[2][128 * SROW];
    __shared__ __align__(16) __nv_bfloat16 sB[2][128 * SROW];

    const int tid = threadIdx.x, lane = tid & 31, wid = tid >> 5;
    const int bn0 = blockIdx.x * 128, bm0 = blockIdx.y * 128;
    const int wm = wid >> 2, wn = wid & 3;

    const uint32_t sAb = smem_to_u32(sA);
    const uint32_t sBb = smem_to_u32(sB);
    const int rowoff = ((lane >> 3) & 1) * 8 + (lane & 7);
    const int kkoff  = (lane >> 4) * 8;
    const int lrow = tid >> 2, lj = tid & 3;

    float acc[4][4][4];
#pragma unroll
    for (int i = 0; i < 4; ++i)
#pragma unroll
        for (int j = 0; j < 4; ++j)
#pragma unroll
            for (int r = 0; r < 4; ++r) acc[i][j][r] = 0.f;

#pragma unroll
    for (int q = 0; q < 2; ++q) {
        int row = lrow + q * 64;
        CP_ASYNC16(sAb + row * 80 + lj * 16, g_xbf + (size_t)(bm0 + row) * KP + lj * 8);
        CP_ASYNC16(sBb + row * 80 + lj * 16, g_Wbp + (size_t)(bn0 + row) * KP + lj * 8);
    }
    CP_COMMIT();

    int buf = 0;
    for (int ch = 0; ch < PNCH; ++ch) {
        if (ch + 1 < PNCH) {
            const int kb = (ch + 1) * PBK;
            const uint32_t da = sAb + (buf ^ 1) * (128 * SROW * 2);
            const uint32_t db = sBb + (buf ^ 1) * (128 * SROW * 2);
#pragma unroll
            for (int q = 0; q < 2; ++q) {
                int row = lrow + q * 64;
                CP_ASYNC16(da + row * 80 + lj * 16, g_xbf + (size_t)(bm0 + row) * KP + kb + lj * 8);
                CP_ASYNC16(db + row * 80 + lj * 16, g_Wbp + (size_t)(bn0 + row) * KP + kb + lj * 8);
            }
            CP_COMMIT();
            CP_WAIT(1);
        } else {
            CP_WAIT(0);
        }
        __syncthreads();
        const uint32_t aBase = sAb + buf * (128 * SROW * 2);
        const uint32_t bBase = sBb + buf * (128 * SROW * 2);
#pragma unroll
        for (int k0 = 0; k0 < PBK; k0 += 16) {
            uint32_t af[4][4], bfr[2][4];
#pragma unroll
            for (int mt = 0; mt < 4; ++mt)
                ldsm_x4(af[mt][0], af[mt][1], af[mt][2], af[mt][3],
                        aBase + (uint32_t)(((wm * 64 + mt * 16 + rowoff) * SROW + k0 + kkoff) * 2));
#pragma unroll
            for (int pt = 0; pt < 2; ++pt)
                ldsm_x4(bfr[pt][0], bfr[pt][1], bfr[pt][2], bfr[pt][3],
                        bBase + (uint32_t)(((wn * 32 + pt * 16 + rowoff) * SROW + k0 + kkoff) * 2));
#pragma unroll
            for (int mt = 0; mt < 4; ++mt)
#pragma unroll
                for (int nt = 0; nt < 4; ++nt) {
                    int pt = nt >> 1, hi = nt & 1;
                    mma16816(acc[mt][nt], af[mt], bfr[pt][hi], bfr[pt][hi + 2]);
                }
        }
        __syncthreads();
        buf ^= 1;
    }

    // epilogue -> xg [cta 256][t][row 64][16 cols(u*4+gate)], bias folded
    const int erow = lane >> 2, ecol = (lane & 3) * 2;
#pragma unroll
    for (int mt = 0; mt < 4; ++mt)
#pragma unroll
        for (int nt = 0; nt < 4; ++nt) {
            int r = bm0 + wm * 64 + mt * 16 + erow;     // m = t*64 + b
            int c = bn0 + wn * 32 + nt * 8 + ecol;
            int tt = r >> 6, b = r & 63;
            int gate = c >> 10, hid = c & 1023, cta = hid >> 2, u = hid & 3;
            size_t base = (size_t)cta * (512 * 64 * 16) + (size_t)tt * 1024 + b * 16 + u * 4 + gate;
            float b0 = g_bsum[c], b1 = g_bsum[c + 1];
            g_xg[base]           = acc[mt][nt][0] + b0;
            g_xg[base + 4]       = acc[mt][nt][1] + b1;   // unit u+1
            g_xg[base + 128]     = acc[mt][nt][2] + b0;   // row b+8
            g_xg[base + 128 + 4] = acc[mt][nt][3] + b1;
        }
}

// ---------------- grid barrier ----------------
__device__ __forceinline__ void grid_sync(unsigned nb)
{
    __threadfence();
    __syncthreads();
    if (threadIdx.x == 0) {
        unsigned gen = *(volatile unsigned*)&g_bar_gen;
        unsigned arr = atomicAdd(&g_bar_cnt, 1);
        if (arr == nb - 1) {
            g_bar_cnt = 0;
            __threadfence();
            *(volatile unsigned*)&g_bar_gen = gen + 1;
        } else {
            while (*(volatile unsigned*)&g_bar_gen == gen) { __nanosleep(32); }
        }
    }
    __syncthreads();
}

// ---------------- HMMA persistent recurrence: 256 CTAs x 256 thr, full operand reuse ----------------
// CTA owns 4 units x 4 gates (col = u*4+gate, 16 cols). Bs phys: [W_hi 1024 | W_lo 1024], pitch 2056
// (row stride 1028 words = 4 mod 32 -> ldsm conflict-free). Warps: mgrp = wid>>2 (2 m-tiles),
// ks = wid&3 (16 phys k-tiles). Per k-tile: load A_hi,A_lo (per mt) + B_hi,B_lo once, issue all
// 3 split terms. LDG/CTA 768->512, LDSM/CTA 768->256 vs R8.
#define BP       2056
#define REC_BS   (16 * BP * 2)                  // 65792
#define REC_SMEM (REC_BS + 4 * 64 * 16 * 4)     // +16384 = 82176

__global__ __launch_bounds__(256, 2) void lstm_rec_mma(
    const float* __restrict__ Whf, const float* __restrict__ Whi,
    const float* __restrict__ Whg, const float* __restrict__ Who,
    float* __restrict__ out)
{
    extern __shared__ __align__(16) char smr[];
    __nv_bfloat16* Bs = (__nv_bfloat16*)smr;
    float* red = (float*)(smr + REC_BS);     // [ks 4][row 64][col 16]

    const int tid = threadIdx.x, lane = tid & 31, wid = tid >> 5;
    const int cta = blockIdx.x;              // 0..255
    const int mgrp = wid >> 2, ks = wid & 3; // SMSP = wid&3
    const unsigned NB = gridDim.x;

    // fill Wh' slice (col = u*4+gate): phys [hi | lo]
    for (int idx = tid; idx < 16 * 1024; idx += 256) {
        int c = idx & 15, k = idx >> 4;
        int u = c >> 2, gate = c & 3;
        const float* W = (gate == 0) ? Whf : (gate == 1) ? Whi : (gate == 2) ? Whg : Who;
        float v = W[(size_t)k * Hdim + cta * 4 + u];
        __nv_bfloat16 hi = __float2bfloat16(v);
        __nv_bfloat16 lo = __float2bfloat16(v - __bfloat162float(hi));
        Bs[c * BP + k]        = hi;
        Bs[c * BP + 1024 + k] = lo;
    }
    // zero h buf0: 65536 u32 over 256*256 threads
    g_hF[cta * 256 + tid] = 0u;
    grid_sync(NB);

    const uint32_t Bbase = smem_to_u32(Bs);
    const int rowoff = ((lane >> 3) & 1) * 8 + (lane & 7);
    const int kkoff  = (lane >> 4) * 8;
    const int erow   = lane >> 2;
    const int uu     = (lane & 3) * 2;
    // cell identity: one thread per (row, unit)
    const int crow = tid >> 2, cu = tid & 3;
    const int K    = cta * 4 + cu;
    const size_t ctaSlab = (size_t)cta * (512 * 64 * 16);
    const int pmt = crow >> 4, prr = crow & 15;
    const int c16 = K & 15;
    const int plane = (prr & 7) * 4 + ((c16 >> 1) & 3);
    const int preg  = (prr >> 3) + 2 * (c16 >> 3);
    const int phalf = K & 1;
    const int ktHi = K >> 4, ktLo = 64 + (K >> 4);
    float cst = 0.f;

    const int kt0 = ks * 16;
    const int mtb = mgrp * 2;

    for (int t = 0; t < Tlen; ++t) {
        const uint32_t* __restrict__ hF = g_hF + (size_t)(t & 1) * 65536;
        float4 xv = *(const float4*)(g_xg + ctaSlab + (size_t)t * 1024 + crow * 16 + cu * 4);

        float acc[2][2][4];   // [mi][nt(col half)][frag]
#pragma unroll
        for (int i = 0; i < 2; ++i)
#pragma unroll
            for (int j = 0; j < 2; ++j)
#pragma unroll
                for (int r = 0; r < 4; ++r) acc[i][j][r] = 0.f;

        // preload k-tile 0 A-fragments (hi and lo) for both m-tiles
        uint4 ahi[2], alo[2], nhi[2], nlo[2];
#pragma unroll
        for (int mi = 0; mi < 2; ++mi) {
            ahi[mi] = *(const uint4*)(hF + ((kt0 * 4 + mtb + mi) * 32 + lane) * 4);
            alo[mi] = *(const uint4*)(hF + (((kt0 + 64) * 4 + mtb + mi) * 32 + lane) * 4);
        }
#pragma unroll 2
        for (int s = 0; s < 16; ++s) {
            const int kt = kt0 + s;
            if (s < 15) {
#pragma unroll
                for (int mi = 0; mi < 2; ++mi) {
                    nhi[mi] = *(const uint4*)(hF + (((kt + 1) * 4 + mtb + mi) * 32 + lane) * 4);
                    nlo[mi] = *(const uint4*)(hF + (((kt + 65) * 4 + mtb + mi) * 32 + lane) * 4);
                }
            }
            uint32_t bh[4], bl[4];
            ldsm_x4(bh[0], bh[1], bh[2], bh[3],
                    Bbase + (uint32_t)((rowoff * BP + kt * 16 + kkoff) * 2));
            ldsm_x4(bl[0], bl[1], bl[2], bl[3],
                    Bbase + (uint32_t)((rowoff * BP + 1024 + kt * 16 + kkoff) * 2));
#pragma unroll
            for (int mi = 0; mi < 2; ++mi) {
                uint32_t ah[4] = {ahi[mi].x, ahi[mi].y, ahi[mi].z, ahi[mi].w};
                uint32_t al[4] = {alo[mi].x, alo[mi].y, alo[mi].z, alo[mi].w};
                mma16816(acc[mi][0], ah, bh[0], bh[2]);   // A_hi * W_hi, cols 0-7
                mma16816(acc[mi][1], ah, bh[1], bh[3]);   // cols 8-15
                mma16816(acc[mi][0], al, bh[0], bh[2]);   // A_lo * W_hi
                mma16816(acc[mi][1], al, bh[1], bh[3]);
                mma16816(acc[mi][0], ah, bl[0], bl[2]);   // A_hi * W_lo
                mma16816(acc[mi][1], ah, bl[1], bl[3]);
            }
#pragma unroll
            for (int mi = 0; mi < 2; ++mi) { ahi[mi] = nhi[mi]; alo[mi] = nlo[mi]; }
        }

        // write partials: red[ks][row][col]
#pragma unroll
        for (int mi = 0; mi < 2; ++mi) {
            const int mt = mtb + mi;
#pragma unroll
            for (int nt = 0; nt < 2; ++nt) {
                int base = (ks * 64 + mt * 16 + erow) * 16 + nt * 8 + uu;
                *(float2*)&red[base]       = make_float2(acc[mi][nt][0], acc[mi][nt][1]);
                *(float2*)&red[base + 128] = make_float2(acc[mi][nt][2], acc[mi][nt][3]); // row +8
            }
        }
        __syncthreads();
        // cell phase: 256 threads, one (row, unit) each; gate quad contiguous
        {
            const float4* r4 = (const float4*)red;
            float4 s0 = r4[(0 * 64 + crow) * 4 + cu];
            float4 s1 = r4[(1 * 64 + crow) * 4 + cu];
            float4 s2 = r4[(2 * 64 + crow) * 4 + cu];
            float4 s3 = r4[(3 * 64 + crow) * 4 + cu];
            float pf = s0.x + s1.x + s2.x + s3.x + xv.x;
            float pi = s0.y + s1.y + s2.y + s3.y + xv.y;
            float pg = s0.z + s1.z + s2.z + s3.z + xv.z;
            float po = s0.w + s1.w + s2.w + s3.w + xv.w;
            float f  = sigf(pf);
            float ii = sigf(pi);
            float gg = tanhf(pg);
            float oo = sigf(po);
            float cn = f * cst + ii * gg;
            cst = cn;
            float hn = tanhf(cn) * oo;
            __nv_bfloat16 hi = __float2bfloat16(hn);
            __nv_bfloat16 lo = __float2bfloat16(hn - __bfloat162float(hi));
            __nv_bfloat16* hw = (__nv_bfloat16*)(g_hF + (size_t)((t + 1) & 1) * 65536);
            hw[(((ktHi * 4 + pmt) * 32 + plane) * 4 + preg) * 2 + phalf] = hi;
            hw[(((ktLo * 4 + pmt) * 32 + plane) * 4 + preg) * 2 + phalf] = lo;
            if (t == Tlen - 1) {
                out[crow * 1024 + K]         = hn;
                out[65536 + crow * 1024 + K] = cn;
            }
        }
        grid_sync(NB);
    }
}

// ---------------- launch ----------------
extern "C" void kernel_launch(void* const* d_in, const int* in_sizes, int n_in,
                              void* d_out, int out_size)
{
    // metadata order = setup_inputs() dict order:
    // 0:x, 1:W_ii, 2:W_hi, 3:W_if, 4:W_hf, 5:W_ig, 6:W_hg, 7:W_io, 8:W_ho,
    // 9:b_ii, 10:b_hi, 11:b_if, 12:b_hf, 13:b_ig, 14:b_hg, 15:b_io, 16:b_ho
    const float* x   = (const float*)d_in[0];
    const float* Wii = (const float*)d_in[1];
    const float* Whi = (const float*)d_in[2];
    const float* Wif = (const float*)d_in[3];
    const float* Whf = (const float*)d_in[4];
    const float* Wig = (const float*)d_in[5];
    const float* Whg = (const float*)d_in[6];
    const float* Wio = (const float*)d_in[7];
    const float* Who = (const float*)d_in[8];
    const float* bii = (const float*)d_in[9];
    const float* bhi = (const float*)d_in[10];
    const float* bif = (const float*)d_in[11];
    const float* bhf = (const float*)d_in[12];
    const float* big = (const float*)d_in[13];
    const float* bhg = (const float*)d_in[14];
    const float* bio = (const float*)d_in[15];
    const float* bho = (const float*)d_in[16];
    float* out = (float*)d_out;

    packW_kernel<<<dim3(16, 16, 4), 256>>>(Wif, Wii, Wig, Wio);
    bias_kernel<<<16, 256>>>(bif, bhf, bii, bhi, big, bhg, bio, bho);
    xconv_kernel<<<Tlen * Bsz, 256>>>(x);
    proj_mma_kernel<<<dim3(G4 / 128, (Tlen * Bsz) / 128), 256>>>();
    cudaFuncSetAttribute(lstm_rec_mma, cudaFuncAttributeMaxDynamicSharedMemorySize, REC_SMEM);
    lstm_rec_mma<<<256, 256, REC_SMEM>>>(Whf, Whi, Whg, Who, out);
}

// round 13
// speedup vs baseline: 1.5603x; 1.0184x over previous
#include <cuda_runtime.h>
#include <cuda_bf16.h>
#include <math.h>
#include <stdint.h>

// LSTM: B=64, T=512, I=H=1024. Output: h_T [64,1024] then c_T [64,1024] (fp32).
#define Bsz  64
#define Tlen 512
#define Idim 1024
#define Hdim 1024
#define G4   4096
#define KP   3072   // 3*1024 hi/lo-split K

// ---------------- scratch ----------------
// g_xg: [cta 256][t 512][row 64][16 cols(unit*4+gate)], gates f,i,g,o
__device__ __align__(16) float         g_xg[(size_t)Tlen * Bsz * G4];
__device__ __align__(16) __nv_bfloat16 g_xbf[(size_t)Tlen * Bsz * KP]; // [m][3072] A'=[x_hi|x_lo|x_hi]
__device__ __align__(16) __nv_bfloat16 g_Wbp[(size_t)G4 * KP];          // [n][3072] B'=[W_hi|W_hi|W_lo]
__device__ __align__(16) float         g_bsum[G4];
// h' double buf, MMA A-fragment layout: [buf 2][kt 128 (0-63 hi,64-127 lo)][mt 4][lane 32][reg 4] u32
__device__ __align__(16) uint32_t      g_hF[2 * 128 * 4 * 32 * 4];
__device__ unsigned g_bar_cnt;
__device__ unsigned g_bar_gen;

// ---------------- helpers ----------------
__device__ __forceinline__ uint32_t smem_to_u32(const void* p) {
    uint32_t a;
    asm("{ .reg .u64 t; cvta.to.shared.u64 t, %1; cvt.u32.u64 %0, t; }" : "=r"(a) : "l"(p));
    return a;
}
__device__ __forceinline__ void ldsm_x4(uint32_t& r0, uint32_t& r1, uint32_t& r2, uint32_t& r3,
                                        uint32_t addr) {
    asm volatile("ldmatrix.sync.aligned.m8n8.x4.shared.b16 {%0,%1,%2,%3}, [%4];"
                 : "=r"(r0), "=r"(r1), "=r"(r2), "=r"(r3) : "r"(addr));
}
__device__ __forceinline__ void mma16816(float* c, const uint32_t* a, uint32_t b0, uint32_t b1) {
    asm volatile(
        "mma.sync.aligned.m16n8k16.row.col.f32.bf16.bf16.f32 "
        "{%0,%1,%2,%3}, {%4,%5,%6,%7}, {%8,%9}, {%0,%1,%2,%3};"
        : "+f"(c[0]), "+f"(c[1]), "+f"(c[2]), "+f"(c[3])
        : "r"(a[0]), "r"(a[1]), "r"(a[2]), "r"(a[3]), "r"(b0), "r"(b1));
}
__device__ __forceinline__ float sigf(float x) { return 1.f / (1.f + __expf(-x)); }
#define CP_ASYNC16(dst, src) \
    asm volatile("cp.async.cg.shared.global [%0], [%1], 16;" :: "r"(dst), "l"(src) : "memory")
#define CP_COMMIT() asm volatile("cp.async.commit_group;" ::: "memory")
#define CP_WAIT(n)  asm volatile("cp.async.wait_group %0;" :: "n"(n) : "memory")

// ---------------- packW ----------------
__global__ __launch_bounds__(256) void packW_kernel(
    const float* __restrict__ Wif, const float* __restrict__ Wii,
    const float* __restrict__ Wig, const float* __restrict__ Wio)
{
    __shared__ float ts[64][65];
    const int tid = threadIdx.x;
    const int k0 = blockIdx.x * 64, h0 = blockIdx.y * 64, gate = blockIdx.z;
    const float* W = (gate == 0) ? Wif : (gate == 1) ? Wii : (gate == 2) ? Wig : Wio;
#pragma unroll
    for (int q = 0; q < 16; ++q) {
        int i = tid + q * 256;
        int r = i >> 6, c = i & 63;
        ts[r][c] = W[(size_t)(k0 + r) * Hdim + h0 + c];
    }
    __syncthreads();
#pragma unroll
    for (int q = 0; q < 16; ++q) {
        int i = tid + q * 256;
        int h = i >> 6, kk = i & 63;
        float v = ts[kk][h];
        __nv_bfloat16 hi = __float2bfloat16(v);
        __nv_bfloat16 lo = __float2bfloat16(v - __bfloat162float(hi));
        size_t base = (size_t)(gate * 1024 + h0 + h) * KP + k0 + kk;
        g_Wbp[base]        = hi;
        g_Wbp[base + 1024] = hi;
        g_Wbp[base + 2048] = lo;
    }
}
__global__ void bias_kernel(const float* __restrict__ bif_, const float* __restrict__ bhf,
                            const float* __restrict__ bii_, const float* __restrict__ bhi,
                            const float* __restrict__ big_, const float* __restrict__ bhg,
                            const float* __restrict__ bio_, const float* __restrict__ bho)
{
    int idx = blockIdx.x * blockDim.x + threadIdx.x;
    if (idx >= G4) return;
    int gate = idx >> 10, hid = idx & 1023;
    const float* bx = (gate == 0) ? bif_ : (gate == 1) ? bii_ : (gate == 2) ? big_ : bio_;
    const float* bh = (gate == 0) ? bhf  : (gate == 1) ? bhi  : (gate == 2) ? bhg  : bho;
    g_bsum[idx] = bx[hid] + bh[hid];
}

// ---------------- xconv ----------------
__global__ __launch_bounds__(256) void xconv_kernel(const float* __restrict__ x)
{
    const int m = blockIdx.x;
    const int b = m & 63, t = m >> 6;
    const float4* __restrict__ xr = (const float4*)(x + (size_t)(b * Tlen + t) * Idim);
    uint32_t* __restrict__ dst = (uint32_t*)(g_xbf + (size_t)m * KP);
    const int j = threadIdx.x;
    float4 v = xr[j];
    __nv_bfloat16 h0 = __float2bfloat16(v.x), h1 = __float2bfloat16(v.y);
    __nv_bfloat16 h2 = __float2bfloat16(v.z), h3 = __float2bfloat16(v.w);
    __nv_bfloat16 l0 = __float2bfloat16(v.x - __bfloat162float(h0));
    __nv_bfloat16 l1 = __float2bfloat16(v.y - __bfloat162float(h1));
    __nv_bfloat16 l2 = __float2bfloat16(v.z - __bfloat162float(h2));
    __nv_bfloat16 l3 = __float2bfloat16(v.w - __bfloat162float(h3));
    uint32_t hp0 = (uint32_t)__bfloat16_as_ushort(h0) | ((uint32_t)__bfloat16_as_ushort(h1) << 16);
    uint32_t hp1 = (uint32_t)__bfloat16_as_ushort(h2) | ((uint32_t)__bfloat16_as_ushort(h3) << 16);
    uint32_t lp0 = (uint32_t)__bfloat16_as_ushort(l0) | ((uint32_t)__bfloat16_as_ushort(l1) << 16);
    uint32_t lp1 = (uint32_t)__bfloat16_as_ushort(l2) | ((uint32_t)__bfloat16_as_ushort(l3) << 16);
    dst[j * 2]        = hp0; dst[j * 2 + 1]        = hp1;
    dst[512 + j * 2]  = lp0; dst[512 + j * 2 + 1]  = lp1;
    dst[1024 + j * 2] = hp0; dst[1024 + j * 2 + 1] = hp1;
}

// ---------------- HMMA input projection, 4-stage cp.async pipeline ----------------
#define PBK    32
#define PNCH   (KP / PBK)   // 96
#define SROW   40
#define NSTG   4
#define BUFB   (128 * SROW * 2)   // 10240 B per matrix per stage

__global__ __launch_bounds__(256, 2) void proj_mma_kernel()
{
    __shared__ __align__(16) __nv_bfloat16 sA[NSTG][128 * SROW];
    __shared__ __align__(16) __nv_bfloat16 sB[NSTG][128 * SROW];

    const int tid = threadIdx.x, lane = tid & 31, wid = tid >> 5;
    const int bn0 = blockIdx.x * 128, bm0 = blockIdx.y * 128;
    const int wm = wid >> 2, wn = wid & 3;

    const uint32_t sAb = smem_to_u32(sA);
    const uint32_t sBb = smem_to_u32(sB);
    const int rowoff = ((lane >> 3) & 1) * 8 + (lane & 7);
    const int kkoff  = (lane >> 4) * 8;
    const int lrow = tid >> 2, lj = tid & 3;

    float acc[4][4][4];
#pragma unroll
    for (int i = 0; i < 4; ++i)
#pragma unroll
        for (int j = 0; j < 4; ++j)
#pragma unroll
            for (int r = 0; r < 4; ++r) acc[i][j][r] = 0.f;

    // prologue: issue chunks 0,1,2
#pragma unroll
    for (int pc = 0; pc < NSTG - 1; ++pc) {
        const uint32_t da = sAb + pc * BUFB;
        const uint32_t db = sBb + pc * BUFB;
        const int kb = pc * PBK;
#pragma unroll
        for (int q = 0; q < 2; ++q) {
            int row = lrow + q * 64;
            CP_ASYNC16(da + row * 80 + lj * 16, g_xbf + (size_t)(bm0 + row) * KP + kb + lj * 8);
            CP_ASYNC16(db + row * 80 + lj * 16, g_Wbp + (size_t)(bn0 + row) * KP + kb + lj * 8);
        }
        CP_COMMIT();
    }

    for (int ch = 0; ch < PNCH; ++ch) {
        // wait for chunk ch to land
        if (ch < PNCH - 2)      CP_WAIT(2);
        else if (ch == PNCH - 2) CP_WAIT(1);
        else                     CP_WAIT(0);
        __syncthreads();   // visibility of chunk ch + all warps done with ch-1

        const int buf = ch & (NSTG - 1);
        const uint32_t aBase = sAb + buf * BUFB;
        const uint32_t bBase = sBb + buf * BUFB;
#pragma unroll
        for (int k0 = 0; k0 < PBK; k0 += 16) {
            uint32_t af[4][4], bfr[2][4];
#pragma unroll
            for (int mt = 0; mt < 4; ++mt)
                ldsm_x4(af[mt][0], af[mt][1], af[mt][2], af[mt][3],
                        aBase + (uint32_t)(((wm * 64 + mt * 16 + rowoff) * SROW + k0 + kkoff) * 2));
#pragma unroll
            for (int pt = 0; pt < 2; ++pt)
                ldsm_x4(bfr[pt][0], bfr[pt][1], bfr[pt][2], bfr[pt][3],
                        bBase + (uint32_t)(((wn * 32 + pt * 16 + rowoff) * SROW + k0 + kkoff) * 2));
#pragma unroll
            for (int mt = 0; mt < 4; ++mt)
#pragma unroll
                for (int nt = 0; nt < 4; ++nt) {
                    int pt = nt >> 1, hi = nt & 1;
                    mma16816(acc[mt][nt], af[mt], bfr[pt][hi], bfr[pt][hi + 2]);
                }
        }
        // issue chunk ch+3 into buffer (ch+3)%4 (its last consumer was chunk ch-1;
        // all warps passed this iteration's __syncthreads after computing ch-1)
        if (ch + NSTG - 1 < PNCH) {
            const int nc = ch + NSTG - 1;
            const int nbuf = nc & (NSTG - 1);
            const uint32_t da = sAb + nbuf * BUFB;
            const uint32_t db = sBb + nbuf * BUFB;
            const int kb = nc * PBK;
#pragma unroll
            for (int q = 0; q < 2; ++q) {
                int row = lrow + q * 64;
                CP_ASYNC16(da + row * 80 + lj * 16, g_xbf + (size_t)(bm0 + row) * KP + kb + lj * 8);
                CP_ASYNC16(db + row * 80 + lj * 16, g_Wbp + (size_t)(bn0 + row) * KP + kb + lj * 8);
            }
            CP_COMMIT();
        }
    }

    // epilogue -> xg [cta 256][t][row 64][16 cols(u*4+gate)], bias folded
    const int erow = lane >> 2, ecol = (lane & 3) * 2;
#pragma unroll
    for (int mt = 0; mt < 4; ++mt)
#pragma unroll
        for (int nt = 0; nt < 4; ++nt) {
            int r = bm0 + wm * 64 + mt * 16 + erow;     // m = t*64 + b
            int c = bn0 + wn * 32 + nt * 8 + ecol;
            int tt = r >> 6, b = r & 63;
            int gate = c >> 10, hid = c & 1023, cta = hid >> 2, u = hid & 3;
            size_t base = (size_t)cta * (512 * 64 * 16) + (size_t)tt * 1024 + b * 16 + u * 4 + gate;
            float b0 = g_bsum[c], b1 = g_bsum[c + 1];
            g_xg[base]           = acc[mt][nt][0] + b0;
            g_xg[base + 4]       = acc[mt][nt][1] + b1;   // unit u+1
            g_xg[base + 128]     = acc[mt][nt][2] + b0;   // row b+8
            g_xg[base + 128 + 4] = acc[mt][nt][3] + b1;
        }
}

// ---------------- grid barrier ----------------
__device__ __forceinline__ void grid_sync(unsigned nb)
{
    __threadfence();
    __syncthreads();
    if (threadIdx.x == 0) {
        unsigned gen = *(volatile unsigned*)&g_bar_gen;
        unsigned arr = atomicAdd(&g_bar_cnt, 1);
        if (arr == nb - 1) {
            g_bar_cnt = 0;
            __threadfence();
            *(volatile unsigned*)&g_bar_gen = gen + 1;
        } else {
            while (*(volatile unsigned*)&g_bar_gen == gen) { __nanosleep(32); }
        }
    }
    __syncthreads();
}

// ---------------- HMMA persistent recurrence (unchanged from passing R10) ----------------
#define BP       2056
#define REC_BS   (16 * BP * 2)                  // 65792
#define REC_SMEM (REC_BS + 4 * 64 * 16 * 4)     // +16384 = 82176

__global__ __launch_bounds__(256, 2) void lstm_rec_mma(
    const float* __restrict__ Whf, const float* __restrict__ Whi,
    const float* __restrict__ Whg, const float* __restrict__ Who,
    float* __restrict__ out)
{
    extern __shared__ __align__(16) char smr[];
    __nv_bfloat16* Bs = (__nv_bfloat16*)smr;
    float* red = (float*)(smr + REC_BS);     // [ks 4][row 64][col 16]

    const int tid = threadIdx.x, lane = tid & 31, wid = tid >> 5;
    const int cta = blockIdx.x;              // 0..255
    const int mgrp = wid >> 2, ks = wid & 3;
    const unsigned NB = gridDim.x;

    for (int idx = tid; idx < 16 * 1024; idx += 256) {
        int c = idx & 15, k = idx >> 4;
        int u = c >> 2, gate = c & 3;
        const float* W = (gate == 0) ? Whf : (gate == 1) ? Whi : (gate == 2) ? Whg : Who;
        float v = W[(size_t)k * Hdim + cta * 4 + u];
        __nv_bfloat16 hi = __float2bfloat16(v);
        __nv_bfloat16 lo = __float2bfloat16(v - __bfloat162float(hi));
        Bs[c * BP + k]        = hi;
        Bs[c * BP + 1024 + k] = lo;
    }
    g_hF[cta * 256 + tid] = 0u;
    grid_sync(NB);

    const uint32_t Bbase = smem_to_u32(Bs);
    const int rowoff = ((lane >> 3) & 1) * 8 + (lane & 7);
    const int kkoff  = (lane >> 4) * 8;
    const int erow   = lane >> 2;
    const int uu     = (lane & 3) * 2;
    const int crow = tid >> 2, cu = tid & 3;
    const int K    = cta * 4 + cu;
    const size_t ctaSlab = (size_t)cta * (512 * 64 * 16);
    const int pmt = crow >> 4, prr = crow & 15;
    const int c16 = K & 15;
    const int plane = (prr & 7) * 4 + ((c16 >> 1) & 3);
    const int preg  = (prr >> 3) + 2 * (c16 >> 3);
    const int phalf = K & 1;
    const int ktHi = K >> 4, ktLo = 64 + (K >> 4);
    float cst = 0.f;

    const int kt0 = ks * 16;
    const int mtb = mgrp * 2;

    for (int t = 0; t < Tlen; ++t) {
        const uint32_t* __restrict__ hF = g_hF + (size_t)(t & 1) * 65536;
        float4 xv = *(const float4*)(g_xg + ctaSlab + (size_t)t * 1024 + crow * 16 + cu * 4);

        float acc[2][2][4];
#pragma unroll
        for (int i = 0; i < 2; ++i)
#pragma unroll
            for (int j = 0; j < 2; ++j)
#pragma unroll
                for (int r = 0; r < 4; ++r) acc[i][j][r] = 0.f;

        uint4 ahi[2], alo[2], nhi[2], nlo[2];
#pragma unroll
        for (int mi = 0; mi < 2; ++mi) {
            ahi[mi] = *(const uint4*)(hF + ((kt0 * 4 + mtb + mi) * 32 + lane) * 4);
            alo[mi] = *(const uint4*)(hF + (((kt0 + 64) * 4 + mtb + mi) * 32 + lane) * 4);
        }
#pragma unroll 2
        for (int s = 0; s < 16; ++s) {
            const int kt = kt0 + s;
            if (s < 15) {
#pragma unroll
                for (int mi = 0; mi < 2; ++mi) {
                    nhi[mi] = *(const uint4*)(hF + (((kt + 1) * 4 + mtb + mi) * 32 + lane) * 4);
                    nlo[mi] = *(const uint4*)(hF + (((kt + 65) * 4 + mtb + mi) * 32 + lane) * 4);
                }
            }
            uint32_t bh[4], bl[4];
            ldsm_x4(bh[0], bh[1], bh[2], bh[3],
                    Bbase + (uint32_t)((rowoff * BP + kt * 16 + kkoff) * 2));
            ldsm_x4(bl[0], bl[1], bl[2], bl[3],
                    Bbase + (uint32_t)((rowoff * BP + 1024 + kt * 16 + kkoff) * 2));
#pragma unroll
            for (int mi = 0; mi < 2; ++mi) {
                uint32_t ah[4] = {ahi[mi].x, ahi[mi].y, ahi[mi].z, ahi[mi].w};
                uint32_t al[4] = {alo[mi].x, alo[mi].y, alo[mi].z, alo[mi].w};
                mma16816(acc[mi][0], ah, bh[0], bh[2]);
                mma16816(acc[mi][1], ah, bh[1], bh[3]);
                mma16816(acc[mi][0], al, bh[0], bh[2]);
                mma16816(acc[mi][1], al, bh[1], bh[3]);
                mma16816(acc[mi][0], ah, bl[0], bl[2]);
                mma16816(acc[mi][1], ah, bl[1], bl[3]);
            }
#pragma unroll
            for (int mi = 0; mi < 2; ++mi) { ahi[mi] = nhi[mi]; alo[mi] = nlo[mi]; }
        }

#pragma unroll
        for (int mi = 0; mi < 2; ++mi) {
            const int mt = mtb + mi;
#pragma unroll
            for (int nt = 0; nt < 2; ++nt) {
                int base = (ks * 64 + mt * 16 + erow) * 16 + nt * 8 + uu;
                *(float2*)&red[base]       = make_float2(acc[mi][nt][0], acc[mi][nt][1]);
                *(float2*)&red[base + 128] = make_float2(acc[mi][nt][2], acc[mi][nt][3]);
            }
        }
        __syncthreads();
        {
            const float4* r4 = (const float4*)red;
            float4 s0 = r4[(0 * 64 + crow) * 4 + cu];
            float4 s1 = r4[(1 * 64 + crow) * 4 + cu];
            float4 s2 = r4[(2 * 64 + crow) * 4 + cu];
            float4 s3 = r4[(3 * 64 + crow) * 4 + cu];
            float pf = s0.x + s1.x + s2.x + s3.x + xv.x;
            float pi = s0.y + s1.y + s2.y + s3.y + xv.y;
            float pg = s0.z + s1.z + s2.z + s3.z + xv.z;
            float po = s0.w + s1.w + s2.w + s3.w + xv.w;
            float f  = sigf(pf);
            float ii = sigf(pi);
            float gg = tanhf(pg);
            float oo = sigf(po);
            float cn = f * cst + ii * gg;
            cst = cn;
            float hn = tanhf(cn) * oo;
            __nv_bfloat16 hi = __float2bfloat16(hn);
            __nv_bfloat16 lo = __float2bfloat16(hn - __bfloat162float(hi));
            __nv_bfloat16* hw = (__nv_bfloat16*)(g_hF + (size_t)((t + 1) & 1) * 65536);
            hw[(((ktHi * 4 + pmt) * 32 + plane) * 4 + preg) * 2 + phalf] = hi;
            hw[(((ktLo * 4 + pmt) * 32 + plane) * 4 + preg) * 2 + phalf] = lo;
            if (t == Tlen - 1) {
                out[crow * 1024 + K]         = hn;
                out[65536 + crow * 1024 + K] = cn;
            }
        }
        grid_sync(NB);
    }
}

// ---------------- launch ----------------
extern "C" void kernel_launch(void* const* d_in, const int* in_sizes, int n_in,
                              void* d_out, int out_size)
{
    // metadata order = setup_inputs() dict order:
    // 0:x, 1:W_ii, 2:W_hi, 3:W_if, 4:W_hf, 5:W_ig, 6:W_hg, 7:W_io, 8:W_ho,
    // 9:b_ii, 10:b_hi, 11:b_if, 12:b_hf, 13:b_ig, 14:b_hg, 15:b_io, 16:b_ho
    const float* x   = (const float*)d_in[0];
    const float* Wii = (const float*)d_in[1];
    const float* Whi = (const float*)d_in[2];
    const float* Wif = (const float*)d_in[3];
    const float* Whf = (const float*)d_in[4];
    const float* Wig = (const float*)d_in[5];
    const float* Whg = (const float*)d_in[6];
    const float* Wio = (const float*)d_in[7];
    const float* Who = (const float*)d_in[8];
    const float* bii = (const float*)d_in[9];
    const float* bhi = (const float*)d_in[10];
    const float* bif = (const float*)d_in[11];
    const float* bhf = (const float*)d_in[12];
    const float* big = (const float*)d_in[13];
    const float* bhg = (const float*)d_in[14];
    const float* bio = (const float*)d_in[15];
    const float* bho = (const float*)d_in[16];
    float* out = (float*)d_out;

    packW_kernel<<<dim3(16, 16, 4), 256>>>(Wif, Wii, Wig, Wio);
    bias_kernel<<<16, 256>>>(bif, bhf, bii, bhi, big, bhg, bio, bho);
    xconv_kernel<<<Tlen * Bsz, 256>>>(x);
    proj_mma_kernel<<<dim3(G4 / 128, (Tlen * Bsz) / 128), 256>>>();
    cudaFuncSetAttribute(lstm_rec_mma, cudaFuncAttributeMaxDynamicSharedMemorySize, REC_SMEM);
    lstm_rec_mma<<<256, 256, REC_SMEM>>>(Whf, Whi, Whg, Who, out);
}

// round 14
// speedup vs baseline: 1.5920x; 1.0203x over previous
#include <cuda_runtime.h>
#include <cuda_bf16.h>
#include <math.h>
#include <stdint.h>

// LSTM: B=64, T=512, I=H=1024. Output: h_T [64,1024] then c_T [64,1024] (fp32).
#define Bsz  64
#define Tlen 512
#define Idim 1024
#define Hdim 1024
#define G4   4096
#define KPH  2048   // physical hi|lo K width

// ---------------- scratch ----------------
// g_xg: [cta 256][t 512][row 64][16 cols(unit*4+gate)], gates f,i,g,o
__device__ __align__(16) float         g_xg[(size_t)Tlen * Bsz * G4];
__device__ __align__(16) __nv_bfloat16 g_xbf[(size_t)Tlen * Bsz * KPH]; // [m][2048] = [x_hi|x_lo]
__device__ __align__(16) __nv_bfloat16 g_Wbp[(size_t)G4 * KPH];          // [n][2048] = [W_hi|W_lo]
__device__ __align__(16) float         g_bsum[G4];
// h' double buf, MMA A-fragment layout: [buf 2][kt 128 (0-63 hi,64-127 lo)][mt 4][lane 32][reg 4] u32
__device__ __align__(16) uint32_t      g_hF[2 * 128 * 4 * 32 * 4];
__device__ unsigned g_bar_cnt;
__device__ unsigned g_bar_gen;

// ---------------- helpers ----------------
__device__ __forceinline__ uint32_t smem_to_u32(const void* p) {
    uint32_t a;
    asm("{ .reg .u64 t; cvta.to.shared.u64 t, %1; cvt.u32.u64 %0, t; }" : "=r"(a) : "l"(p));
    return a;
}
__device__ __forceinline__ void ldsm_x4(uint32_t& r0, uint32_t& r1, uint32_t& r2, uint32_t& r3,
                                        uint32_t addr) {
    asm volatile("ldmatrix.sync.aligned.m8n8.x4.shared.b16 {%0,%1,%2,%3}, [%4];"
                 : "=r"(r0), "=r"(r1), "=r"(r2), "=r"(r3) : "r"(addr));
}
__device__ __forceinline__ void mma16816(float* c, const uint32_t* a, uint32_t b0, uint32_t b1) {
    asm volatile(
        "mma.sync.aligned.m16n8k16.row.col.f32.bf16.bf16.f32 "
        "{%0,%1,%2,%3}, {%4,%5,%6,%7}, {%8,%9}, {%0,%1,%2,%3};"
        : "+f"(c[0]), "+f"(c[1]), "+f"(c[2]), "+f"(c[3])
        : "r"(a[0]), "r"(a[1]), "r"(a[2]), "r"(a[3]), "r"(b0), "r"(b1));
}
__device__ __forceinline__ float sigf(float x) { return 1.f / (1.f + __expf(-x)); }
#define CP_ASYNC16(dst, src) \
    asm volatile("cp.async.cg.shared.global [%0], [%1], 16;" :: "r"(dst), "l"(src) : "memory")
#define CP_COMMIT() asm volatile("cp.async.commit_group;" ::: "memory")
#define CP_WAIT(n)  asm volatile("cp.async.wait_group %0;" :: "n"(n) : "memory")

// ---------------- packW: [n][2048] = [W_hi | W_lo] ----------------
__global__ __launch_bounds__(256) void packW_kernel(
    const float* __restrict__ Wif, const float* __restrict__ Wii,
    const float* __restrict__ Wig, const float* __restrict__ Wio)
{
    __shared__ float ts[64][65];
    const int tid = threadIdx.x;
    const int k0 = blockIdx.x * 64, h0 = blockIdx.y * 64, gate = blockIdx.z;
    const float* W = (gate == 0) ? Wif : (gate == 1) ? Wii : (gate == 2) ? Wig : Wio;
#pragma unroll
    for (int q = 0; q < 16; ++q) {
        int i = tid + q * 256;
        int r = i >> 6, c = i & 63;
        ts[r][c] = W[(size_t)(k0 + r) * Hdim + h0 + c];
    }
    __syncthreads();
#pragma unroll
    for (int q = 0; q < 16; ++q) {
        int i = tid + q * 256;
        int h = i >> 6, kk = i & 63;
        float v = ts[kk][h];
        __nv_bfloat16 hi = __float2bfloat16(v);
        __nv_bfloat16 lo = __float2bfloat16(v - __bfloat162float(hi));
        size_t base = (size_t)(gate * 1024 + h0 + h) * KPH + k0 + kk;
        g_Wbp[base]        = hi;
        g_Wbp[base + 1024] = lo;
    }
}
__global__ void bias_kernel(const float* __restrict__ bif_, const float* __restrict__ bhf,
                            const float* __restrict__ bii_, const float* __restrict__ bhi,
                            const float* __restrict__ big_, const float* __restrict__ bhg,
                            const float* __restrict__ bio_, const float* __restrict__ bho)
{
    int idx = blockIdx.x * blockDim.x + threadIdx.x;
    if (idx >= G4) return;
    int gate = idx >> 10, hid = idx & 1023;
    const float* bx = (gate == 0) ? bif_ : (gate == 1) ? bii_ : (gate == 2) ? big_ : bio_;
    const float* bh = (gate == 0) ? bhf  : (gate == 1) ? bhi  : (gate == 2) ? bhg  : bho;
    g_bsum[idx] = bx[hid] + bh[hid];
}

// ---------------- xconv: [m][2048] = [x_hi | x_lo] ----------------
__global__ __launch_bounds__(256) void xconv_kernel(const float* __restrict__ x)
{
    const int m = blockIdx.x;
    const int b = m & 63, t = m >> 6;
    const float4* __restrict__ xr = (const float4*)(x + (size_t)(b * Tlen + t) * Idim);
    uint32_t* __restrict__ dst = (uint32_t*)(g_xbf + (size_t)m * KPH);
    const int j = threadIdx.x;
    float4 v = xr[j];
    __nv_bfloat16 h0 = __float2bfloat16(v.x), h1 = __float2bfloat16(v.y);
    __nv_bfloat16 h2 = __float2bfloat16(v.z), h3 = __float2bfloat16(v.w);
    __nv_bfloat16 l0 = __float2bfloat16(v.x - __bfloat162float(h0));
    __nv_bfloat16 l1 = __float2bfloat16(v.y - __bfloat162float(h1));
    __nv_bfloat16 l2 = __float2bfloat16(v.z - __bfloat162float(h2));
    __nv_bfloat16 l3 = __float2bfloat16(v.w - __bfloat162float(h3));
    uint32_t hp0 = (uint32_t)__bfloat16_as_ushort(h0) | ((uint32_t)__bfloat16_as_ushort(h1) << 16);
    uint32_t hp1 = (uint32_t)__bfloat16_as_ushort(h2) | ((uint32_t)__bfloat16_as_ushort(h3) << 16);
    uint32_t lp0 = (uint32_t)__bfloat16_as_ushort(l0) | ((uint32_t)__bfloat16_as_ushort(l1) << 16);
    uint32_t lp1 = (uint32_t)__bfloat16_as_ushort(l2) | ((uint32_t)__bfloat16_as_ushort(l3) << 16);
    dst[j * 2]       = hp0; dst[j * 2 + 1]       = hp1;   // x_hi
    dst[512 + j * 2] = lp0; dst[512 + j * 2 + 1] = lp1;   // x_lo
}

// ---------------- HMMA input projection: 32 K-groups, operand reuse, 2-stage pipeline ----------------
// Per group (orig K=32): load A_hi, A_lo, B_hi, B_lo tiles; issue 3 terms:
// A_hi*B_hi, A_lo*B_hi, A_hi*B_lo. cp.async and LDSM both -33% vs duplicated layout.
#define NGRP  32
#define SROW  40
#define BUFB  (128 * SROW * 2)   // 10240 B per tile per stage

__global__ __launch_bounds__(256, 2) void proj_mma_kernel()
{
    __shared__ __align__(16) __nv_bfloat16 sAh[2][128 * SROW];
    __shared__ __align__(16) __nv_bfloat16 sAl[2][128 * SROW];
    __shared__ __align__(16) __nv_bfloat16 sBh[2][128 * SROW];
    __shared__ __align__(16) __nv_bfloat16 sBl[2][128 * SROW];

    const int tid = threadIdx.x, lane = tid & 31, wid = tid >> 5;
    const int bn0 = blockIdx.x * 128, bm0 = blockIdx.y * 128;
    const int wm = wid >> 2, wn = wid & 3;

    const uint32_t sAhb = smem_to_u32(sAh);
    const uint32_t sAlb = smem_to_u32(sAl);
    const uint32_t sBhb = smem_to_u32(sBh);
    const uint32_t sBlb = smem_to_u32(sBl);
    const int rowoff = ((lane >> 3) & 1) * 8 + (lane & 7);
    const int kkoff  = (lane >> 4) * 8;
    const int lrow = tid >> 2, lj = tid & 3;   // 4 x 16B chunks per 64B-wide row

    float acc[4][4][4];
#pragma unroll
    for (int i = 0; i < 4; ++i)
#pragma unroll
        for (int j = 0; j < 4; ++j)
#pragma unroll
            for (int r = 0; r < 4; ++r) acc[i][j][r] = 0.f;

    // prologue: load group 0 into buf 0
#pragma unroll
    for (int q = 0; q < 2; ++q) {
        int row = lrow + q * 64;
        const __nv_bfloat16* xa = g_xbf + (size_t)(bm0 + row) * KPH + lj * 8;
        const __nv_bfloat16* wb = g_Wbp + (size_t)(bn0 + row) * KPH + lj * 8;
        CP_ASYNC16(sAhb + row * 80 + lj * 16, xa);
        CP_ASYNC16(sAlb + row * 80 + lj * 16, xa + 1024);
        CP_ASYNC16(sBhb + row * 80 + lj * 16, wb);
        CP_ASYNC16(sBlb + row * 80 + lj * 16, wb + 1024);
    }
    CP_COMMIT();

    for (int g = 0; g < NGRP; ++g) {
        const int buf = g & 1;
        if (g + 1 < NGRP) {
            const int kb = (g + 1) * 32;
            const uint32_t off = (uint32_t)((buf ^ 1) * BUFB);
#pragma unroll
            for (int q = 0; q < 2; ++q) {
                int row = lrow + q * 64;
                const __nv_bfloat16* xa = g_xbf + (size_t)(bm0 + row) * KPH + kb + lj * 8;
                const __nv_bfloat16* wb = g_Wbp + (size_t)(bn0 + row) * KPH + kb + lj * 8;
                CP_ASYNC16(sAhb + off + row * 80 + lj * 16, xa);
                CP_ASYNC16(sAlb + off + row * 80 + lj * 16, xa + 1024);
                CP_ASYNC16(sBhb + off + row * 80 + lj * 16, wb);
                CP_ASYNC16(sBlb + off + row * 80 + lj * 16, wb + 1024);
            }
            CP_COMMIT();
            CP_WAIT(1);
        } else {
            CP_WAIT(0);
        }
        __syncthreads();   // group g visible; all warps past group g-1 compute

        const uint32_t off = (uint32_t)(buf * BUFB);
#pragma unroll
        for (int k0 = 0; k0 < 32; k0 += 16) {
            uint32_t ah[4][4], al[4][4], bh[2][4], bl[2][4];
#pragma unroll
            for (int mt = 0; mt < 4; ++mt) {
                uint32_t ro = (uint32_t)(((wm * 64 + mt * 16 + rowoff) * SROW + k0 + kkoff) * 2);
                ldsm_x4(ah[mt][0], ah[mt][1], ah[mt][2], ah[mt][3], sAhb + off + ro);
            }
#pragma unroll
            for (int pt = 0; pt < 2; ++pt) {
                uint32_t ro = (uint32_t)(((wn * 32 + pt * 16 + rowoff) * SROW + k0 + kkoff) * 2);
                ldsm_x4(bh[pt][0], bh[pt][1], bh[pt][2], bh[pt][3], sBhb + off + ro);
            }
            // term 1: A_hi * B_hi
#pragma unroll
            for (int mt = 0; mt < 4; ++mt)
#pragma unroll
                for (int nt = 0; nt < 4; ++nt) {
                    int pt = nt >> 1, hb = nt & 1;
                    mma16816(acc[mt][nt], ah[mt], bh[pt][hb], bh[pt][hb + 2]);
                }
            // term 2: A_lo * B_hi
#pragma unroll
            for (int mt = 0; mt < 4; ++mt) {
                uint32_t ro = (uint32_t)(((wm * 64 + mt * 16 + rowoff) * SROW + k0 + kkoff) * 2);
                ldsm_x4(al[mt][0], al[mt][1], al[mt][2], al[mt][3], sAlb + off + ro);
            }
#pragma unroll
            for (int mt = 0; mt < 4; ++mt)
#pragma unroll
                for (int nt = 0; nt < 4; ++nt) {
                    int pt = nt >> 1, hb = nt & 1;
                    mma16816(acc[mt][nt], al[mt], bh[pt][hb], bh[pt][hb + 2]);
                }
            // term 3: A_hi * B_lo
#pragma unroll
            for (int pt = 0; pt < 2; ++pt) {
                uint32_t ro = (uint32_t)(((wn * 32 + pt * 16 + rowoff) * SROW + k0 + kkoff) * 2);
                ldsm_x4(bl[pt][0], bl[pt][1], bl[pt][2], bl[pt][3], sBlb + off + ro);
            }
#pragma unroll
            for (int mt = 0; mt < 4; ++mt)
#pragma unroll
                for (int nt = 0; nt < 4; ++nt) {
                    int pt = nt >> 1, hb = nt & 1;
                    mma16816(acc[mt][nt], ah[mt], bl[pt][hb], bl[pt][hb + 2]);
                }
        }
        __syncthreads();   // protect this buffer before group g+2's loads
    }

    // epilogue -> xg [cta 256][t][row 64][16 cols(u*4+gate)], bias folded
    const int erow = lane >> 2, ecol = (lane & 3) * 2;
#pragma unroll
    for (int mt = 0; mt < 4; ++mt)
#pragma unroll
        for (int nt = 0; nt < 4; ++nt) {
            int r = bm0 + wm * 64 + mt * 16 + erow;     // m = t*64 + b
            int c = bn0 + wn * 32 + nt * 8 + ecol;
            int tt = r >> 6, b = r & 63;
            int gate = c >> 10, hid = c & 1023, cta = hid >> 2, u = hid & 3;
            size_t base = (size_t)cta * (512 * 64 * 16) + (size_t)tt * 1024 + b * 16 + u * 4 + gate;
            float b0 = g_bsum[c], b1 = g_bsum[c + 1];
            g_xg[base]           = acc[mt][nt][0] + b0;
            g_xg[base + 4]       = acc[mt][nt][1] + b1;   // unit u+1
            g_xg[base + 128]     = acc[mt][nt][2] + b0;   // row b+8
            g_xg[base + 128 + 4] = acc[mt][nt][3] + b1;
        }
}

// ---------------- grid barrier ----------------
__device__ __forceinline__ void grid_sync(unsigned nb)
{
    __threadfence();
    __syncthreads();
    if (threadIdx.x == 0) {
        unsigned gen = *(volatile unsigned*)&g_bar_gen;
        unsigned arr = atomicAdd(&g_bar_cnt, 1);
        if (arr == nb - 1) {
            g_bar_cnt = 0;
            __threadfence();
            *(volatile unsigned*)&g_bar_gen = gen + 1;
        } else {
            while (*(volatile unsigned*)&g_bar_gen == gen) { __nanosleep(32); }
        }
    }
    __syncthreads();
}

// ---------------- HMMA persistent recurrence (unchanged from passing R10/R13) ----------------
#define BP       2056
#define REC_BS   (16 * BP * 2)                  // 65792
#define REC_SMEM (REC_BS + 4 * 64 * 16 * 4)     // +16384 = 82176

__global__ __launch_bounds__(256, 2) void lstm_rec_mma(
    const float* __restrict__ Whf, const float* __restrict__ Whi,
    const float* __restrict__ Whg, const float* __restrict__ Who,
    float* __restrict__ out)
{
    extern __shared__ __align__(16) char smr[];
    __nv_bfloat16* Bs = (__nv_bfloat16*)smr;
    float* red = (float*)(smr + REC_BS);     // [ks 4][row 64][col 16]

    const int tid = threadIdx.x, lane = tid & 31, wid = tid >> 5;
    const int cta = blockIdx.x;              // 0..255
    const int mgrp = wid >> 2, ks = wid & 3;
    const unsigned NB = gridDim.x;

    for (int idx = tid; idx < 16 * 1024; idx += 256) {
        int c = idx & 15, k = idx >> 4;
        int u = c >> 2, gate = c & 3;
        const float* W = (gate == 0) ? Whf : (gate == 1) ? Whi : (gate == 2) ? Whg : Who;
        float v = W[(size_t)k * Hdim + cta * 4 + u];
        __nv_bfloat16 hi = __float2bfloat16(v);
        __nv_bfloat16 lo = __float2bfloat16(v - __bfloat162float(hi));
        Bs[c * BP + k]        = hi;
        Bs[c * BP + 1024 + k] = lo;
    }
    g_hF[cta * 256 + tid] = 0u;
    grid_sync(NB);

    const uint32_t Bbase = smem_to_u32(Bs);
    const int rowoff = ((lane >> 3) & 1) * 8 + (lane & 7);
    const int kkoff  = (lane >> 4) * 8;
    const int erow   = lane >> 2;
    const int uu     = (lane & 3) * 2;
    const int crow = tid >> 2, cu = tid & 3;
    const int K    = cta * 4 + cu;
    const size_t ctaSlab = (size_t)cta * (512 * 64 * 16);
    const int pmt = crow >> 4, prr = crow & 15;
    const int c16 = K & 15;
    const int plane = (prr & 7) * 4 + ((c16 >> 1) & 3);
    const int preg  = (prr >> 3) + 2 * (c16 >> 3);
    const int phalf = K & 1;
    const int ktHi = K >> 4, ktLo = 64 + (K >> 4);
    float cst = 0.f;

    const int kt0 = ks * 16;
    const int mtb = mgrp * 2;

    for (int t = 0; t < Tlen; ++t) {
        const uint32_t* __restrict__ hF = g_hF + (size_t)(t & 1) * 65536;
        float4 xv = *(const float4*)(g_xg + ctaSlab + (size_t)t * 1024 + crow * 16 + cu * 4);

        float acc[2][2][4];
#pragma unroll
        for (int i = 0; i < 2; ++i)
#pragma unroll
            for (int j = 0; j < 2; ++j)
#pragma unroll
                for (int r = 0; r < 4; ++r) acc[i][j][r] = 0.f;

        uint4 ahi[2], alo[2], nhi[2], nlo[2];
#pragma unroll
        for (int mi = 0; mi < 2; ++mi) {
            ahi[mi] = *(const uint4*)(hF + ((kt0 * 4 + mtb + mi) * 32 + lane) * 4);
            alo[mi] = *(const uint4*)(hF + (((kt0 + 64) * 4 + mtb + mi) * 32 + lane) * 4);
        }
#pragma unroll 2
        for (int s = 0; s < 16; ++s) {
            const int kt = kt0 + s;
            if (s < 15) {
#pragma unroll
                for (int mi = 0; mi < 2; ++mi) {
                    nhi[mi] = *(const uint4*)(hF + (((kt + 1) * 4 + mtb + mi) * 32 + lane) * 4);
                    nlo[mi] = *(const uint4*)(hF + (((kt + 65) * 4 + mtb + mi) * 32 + lane) * 4);
                }
            }
            uint32_t bh[4], bl[4];
            ldsm_x4(bh[0], bh[1], bh[2], bh[3],
                    Bbase + (uint32_t)((rowoff * BP + kt * 16 + kkoff) * 2));
            ldsm_x4(bl[0], bl[1], bl[2], bl[3],
                    Bbase + (uint32_t)((rowoff * BP + 1024 + kt * 16 + kkoff) * 2));
#pragma unroll
            for (int mi = 0; mi < 2; ++mi) {
                uint32_t ah[4] = {ahi[mi].x, ahi[mi].y, ahi[mi].z, ahi[mi].w};
                uint32_t al[4] = {alo[mi].x, alo[mi].y, alo[mi].z, alo[mi].w};
                mma16816(acc[mi][0], ah, bh[0], bh[2]);
                mma16816(acc[mi][1], ah, bh[1], bh[3]);
                mma16816(acc[mi][0], al, bh[0], bh[2]);
                mma16816(acc[mi][1], al, bh[1], bh[3]);
                mma16816(acc[mi][0], ah, bl[0], bl[2]);
                mma16816(acc[mi][1], ah, bl[1], bl[3]);
            }
#pragma unroll
            for (int mi = 0; mi < 2; ++mi) { ahi[mi] = nhi[mi]; alo[mi] = nlo[mi]; }
        }

#pragma unroll
        for (int mi = 0; mi < 2; ++mi) {
            const int mt = mtb + mi;
#pragma unroll
            for (int nt = 0; nt < 2; ++nt) {
                int base = (ks * 64 + mt * 16 + erow) * 16 + nt * 8 + uu;
                *(float2*)&red[base]       = make_float2(acc[mi][nt][0], acc[mi][nt][1]);
                *(float2*)&red[base + 128] = make_float2(acc[mi][nt][2], acc[mi][nt][3]);
            }
        }
        __syncthreads();
        {
            const float4* r4 = (const float4*)red;
            float4 s0 = r4[(0 * 64 + crow) * 4 + cu];
            float4 s1 = r4[(1 * 64 + crow) * 4 + cu];
            float4 s2 = r4[(2 * 64 + crow) * 4 + cu];
            float4 s3 = r4[(3 * 64 + crow) * 4 + cu];
            float pf = s0.x + s1.x + s2.x + s3.x + xv.x;
            float pi = s0.y + s1.y + s2.y + s3.y + xv.y;
            float pg = s0.z + s1.z + s2.z + s3.z + xv.z;
            float po = s0.w + s1.w + s2.w + s3.w + xv.w;
            float f  = sigf(pf);
            float ii = sigf(pi);
            float gg = tanhf(pg);
            float oo = sigf(po);
            float cn = f * cst + ii * gg;
            cst = cn;
            float hn = tanhf(cn) * oo;
            __nv_bfloat16 hi = __float2bfloat16(hn);
            __nv_bfloat16 lo = __float2bfloat16(hn - __bfloat162float(hi));
            __nv_bfloat16* hw = (__nv_bfloat16*)(g_hF + (size_t)((t + 1) & 1) * 65536);
            hw[(((ktHi * 4 + pmt) * 32 + plane) * 4 + preg) * 2 + phalf] = hi;
            hw[(((ktLo * 4 + pmt) * 32 + plane) * 4 + preg) * 2 + phalf] = lo;
            if (t == Tlen - 1) {
                out[crow * 1024 + K]         = hn;
                out[65536 + crow * 1024 + K] = cn;
            }
        }
        grid_sync(NB);
    }
}

// ---------------- launch ----------------
extern "C" void kernel_launch(void* const* d_in, const int* in_sizes, int n_in,
                              void* d_out, int out_size)
{
    // metadata order = setup_inputs() dict order:
    // 0:x, 1:W_ii, 2:W_hi, 3:W_if, 4:W_hf, 5:W_ig, 6:W_hg, 7:W_io, 8:W_ho,
    // 9:b_ii, 10:b_hi, 11:b_if, 12:b_hf, 13:b_ig, 14:b_hg, 15:b_io, 16:b_ho
    const float* x   = (const float*)d_in[0];
    const float* Wii = (const float*)d_in[1];
    const float* Whi = (const float*)d_in[2];
    const float* Wif = (const float*)d_in[3];
    const float* Whf = (const float*)d_in[4];
    const float* Wig = (const float*)d_in[5];
    const float* Whg = (const float*)d_in[6];
    const float* Wio = (const float*)d_in[7];
    const float* Who = (const float*)d_in[8];
    const float* bii = (const float*)d_in[9];
    const float* bhi = (const float*)d_in[10];
    const float* bif = (const float*)d_in[11];
    const float* bhf = (const float*)d_in[12];
    const float* big = (const float*)d_in[13];
    const float* bhg = (const float*)d_in[14];
    const float* bio = (const float*)d_in[15];
    const float* bho = (const float*)d_in[16];
    float* out = (float*)d_out;

    packW_kernel<<<dim3(16, 16, 4), 256>>>(Wif, Wii, Wig, Wio);
    bias_kernel<<<16, 256>>>(bif, bhf, bii, bhi, big, bhg, bio, bho);
    xconv_kernel<<<Tlen * Bsz, 256>>>(x);
    proj_mma_kernel<<<dim3(G4 / 128, (Tlen * Bsz) / 128), 256>>>();
    cudaFuncSetAttribute(lstm_rec_mma, cudaFuncAttributeMaxDynamicSharedMemorySize, REC_SMEM);
    lstm_rec_mma<<<256, 256, REC_SMEM>>>(Whf, Whi, Whg, Who, out);
}

// round 16
// speedup vs baseline: 1.5965x; 1.0028x over previous
#include <cuda_runtime.h>
#include <cuda_bf16.h>
#include <math.h>
#include <stdint.h>

// LSTM: B=64, T=512, I=H=1024. Output: h_T [64,1024] then c_T [64,1024] (fp32).
#define Bsz  64
#define Tlen 512
#define Idim 1024
#define Hdim 1024
#define G4   4096
#define KPH  2048   // physical hi|lo K width

// ---------------- scratch ----------------
// g_xg: [cta 256][t 512][row 64][16 cols(unit*4+gate)], gates f,i,g,o
__device__ __align__(16) float         g_xg[(size_t)Tlen * Bsz * G4];
__device__ __align__(16) __nv_bfloat16 g_xbf[(size_t)Tlen * Bsz * KPH]; // [m][2048] = [x_hi|x_lo]
__device__ __align__(16) __nv_bfloat16 g_Wbp[(size_t)G4 * KPH];          // [n][2048] = [W_hi|W_lo]
__device__ __align__(16) float         g_bsum[G4];
// h' double buf, MMA A-fragment layout: [buf 2][kt 128 (0-63 hi,64-127 lo)][mt 4][lane 32][reg 4] u32
__device__ __align__(16) uint32_t      g_hF[2 * 128 * 4 * 32 * 4];
__device__ unsigned g_bar_cnt;
__device__ unsigned g_bar_gen;

// ---------------- helpers ----------------
__device__ __forceinline__ uint32_t smem_to_u32(const void* p) {
    uint32_t a;
    asm("{ .reg .u64 t; cvta.to.shared.u64 t, %1; cvt.u32.u64 %0, t; }" : "=r"(a) : "l"(p));
    return a;
}
__device__ __forceinline__ void ldsm_x4(uint32_t& r0, uint32_t& r1, uint32_t& r2, uint32_t& r3,
                                        uint32_t addr) {
    asm volatile("ldmatrix.sync.aligned.m8n8.x4.shared.b16 {%0,%1,%2,%3}, [%4];"
                 : "=r"(r0), "=r"(r1), "=r"(r2), "=r"(r3) : "r"(addr));
}
__device__ __forceinline__ void mma16816(float* c, const uint32_t* a, uint32_t b0, uint32_t b1) {
    asm volatile(
        "mma.sync.aligned.m16n8k16.row.col.f32.bf16.bf16.f32 "
        "{%0,%1,%2,%3}, {%4,%5,%6,%7}, {%8,%9}, {%0,%1,%2,%3};"
        : "+f"(c[0]), "+f"(c[1]), "+f"(c[2]), "+f"(c[3])
        : "r"(a[0]), "r"(a[1]), "r"(a[2]), "r"(a[3]), "r"(b0), "r"(b1));
}
__device__ __forceinline__ float sigf(float x) { return 1.f / (1.f + __expf(-x)); }
// .cg: L2-only (no L1). .ca: caches in L1 — use for data duplicated across co-resident CTAs.
#define CP_ASYNC16_CG(dst, src) \
    asm volatile("cp.async.cg.shared.global [%0], [%1], 16;" :: "r"(dst), "l"(src) : "memory")
#define CP_ASYNC16_CA(dst, src) \
    asm volatile("cp.async.ca.shared.global [%0], [%1], 16;" :: "r"(dst), "l"(src) : "memory")
#define CP_COMMIT() asm volatile("cp.async.commit_group;" ::: "memory")
#define CP_WAIT(n)  asm volatile("cp.async.wait_group %0;" :: "n"(n) : "memory")

// ---------------- packW: [n][2048] = [W_hi | W_lo] ----------------
__global__ __launch_bounds__(256) void packW_kernel(
    const float* __restrict__ Wif, const float* __restrict__ Wii,
    const float* __restrict__ Wig, const float* __restrict__ Wio)
{
    __shared__ float ts[64][65];
    const int tid = threadIdx.x;
    const int k0 = blockIdx.x * 64, h0 = blockIdx.y * 64, gate = blockIdx.z;
    const float* W = (gate == 0) ? Wif : (gate == 1) ? Wii : (gate == 2) ? Wig : Wio;
#pragma unroll
    for (int q = 0; q < 16; ++q) {
        int i = tid + q * 256;
        int r = i >> 6, c = i & 63;
        ts[r][c] = W[(size_t)(k0 + r) * Hdim + h0 + c];
    }
    __syncthreads();
#pragma unroll
    for (int q = 0; q < 16; ++q) {
        int i = tid + q * 256;
        int h = i >> 6, kk = i & 63;
        float v = ts[kk][h];
        __nv_bfloat16 hi = __float2bfloat16(v);
        __nv_bfloat16 lo = __float2bfloat16(v - __bfloat162float(hi));
        size_t base = (size_t)(gate * 1024 + h0 + h) * KPH + k0 + kk;
        g_Wbp[base]        = hi;
        g_Wbp[base + 1024] = lo;
    }
}
__global__ void bias_kernel(const float* __restrict__ bif_, const float* __restrict__ bhf,
                            const float* __restrict__ bii_, const float* __restrict__ bhi,
                            const float* __restrict__ big_, const float* __restrict__ bhg,
                            const float* __restrict__ bio_, const float* __restrict__ bho)
{
    int idx = blockIdx.x * blockDim.x + threadIdx.x;
    if (idx >= G4) return;
    int gate = idx >> 10, hid = idx & 1023;
    const float* bx = (gate == 0) ? bif_ : (gate == 1) ? bii_ : (gate == 2) ? big_ : bio_;
    const float* bh = (gate == 0) ? bhf  : (gate == 1) ? bhi  : (gate == 2) ? bhg  : bho;
    g_bsum[idx] = bx[hid] + bh[hid];
}

// ---------------- xconv: [m][2048] = [x_hi | x_lo] ----------------
__global__ __launch_bounds__(256) void xconv_kernel(const float* __restrict__ x)
{
    const int m = blockIdx.x;
    const int b = m & 63, t = m >> 6;
    const float4* __restrict__ xr = (const float4*)(x + (size_t)(b * Tlen + t) * Idim);
    uint32_t* __restrict__ dst = (uint32_t*)(g_xbf + (size_t)m * KPH);
    const int j = threadIdx.x;
    float4 v = xr[j];
    __nv_bfloat16 h0 = __float2bfloat16(v.x), h1 = __float2bfloat16(v.y);
    __nv_bfloat16 h2 = __float2bfloat16(v.z), h3 = __float2bfloat16(v.w);
    __nv_bfloat16 l0 = __float2bfloat16(v.x - __bfloat162float(h0));
    __nv_bfloat16 l1 = __float2bfloat16(v.y - __bfloat162float(h1));
    __nv_bfloat16 l2 = __float2bfloat16(v.z - __bfloat162float(h2));
    __nv_bfloat16 l3 = __float2bfloat16(v.w - __bfloat162float(h3));
    uint32_t hp0 = (uint32_t)__bfloat16_as_ushort(h0) | ((uint32_t)__bfloat16_as_ushort(h1) << 16);
    uint32_t hp1 = (uint32_t)__bfloat16_as_ushort(h2) | ((uint32_t)__bfloat16_as_ushort(h3) << 16);
    uint32_t lp0 = (uint32_t)__bfloat16_as_ushort(l0) | ((uint32_t)__bfloat16_as_ushort(l1) << 16);
    uint32_t lp1 = (uint32_t)__bfloat16_as_ushort(l2) | ((uint32_t)__bfloat16_as_ushort(l3) << 16);
    dst[j * 2]       = hp0; dst[j * 2 + 1]       = hp1;   // x_hi
    dst[512 + j * 2] = lp0; dst[512 + j * 2 + 1] = lp1;   // x_lo
}

// ---------------- HMMA input projection: 32 K-groups, operand reuse, 2-stage pipeline ----------------
// A tiles via cp.async.ca (co-resident CTA shares bm0 -> duplicate A loads hit L1);
// B tiles via cp.async.cg (no cross-CTA dup).
#define NGRP  32
#define SROW  40
#define BUFB  (128 * SROW * 2)   // 10240 B per tile per stage

__global__ __launch_bounds__(256, 2) void proj_mma_kernel()
{
    __shared__ __align__(16) __nv_bfloat16 sAh[2][128 * SROW];
    __shared__ __align__(16) __nv_bfloat16 sAl[2][128 * SROW];
    __shared__ __align__(16) __nv_bfloat16 sBh[2][128 * SROW];
    __shared__ __align__(16) __nv_bfloat16 sBl[2][128 * SROW];

    const int tid = threadIdx.x, lane = tid & 31, wid = tid >> 5;
    const int bn0 = blockIdx.x * 128, bm0 = blockIdx.y * 128;
    const int wm = wid >> 2, wn = wid & 3;

    const uint32_t sAhb = smem_to_u32(sAh);
    const uint32_t sAlb = smem_to_u32(sAl);
    const uint32_t sBhb = smem_to_u32(sBh);
    const uint32_t sBlb = smem_to_u32(sBl);
    const int rowoff = ((lane >> 3) & 1) * 8 + (lane & 7);
    const int kkoff  = (lane >> 4) * 8;
    const int lrow = tid >> 2, lj = tid & 3;

    float acc[4][4][4];
#pragma unroll
    for (int i = 0; i < 4; ++i)
#pragma unroll
        for (int j = 0; j < 4; ++j)
#pragma unroll
            for (int r = 0; r < 4; ++r) acc[i][j][r] = 0.f;

    // prologue: load group 0 into buf 0
#pragma unroll
    for (int q = 0; q < 2; ++q) {
        int row = lrow + q * 64;
        const __nv_bfloat16* xa = g_xbf + (size_t)(bm0 + row) * KPH + lj * 8;
        const __nv_bfloat16* wb = g_Wbp + (size_t)(bn0 + row) * KPH + lj * 8;
        CP_ASYNC16_CA(sAhb + row * 80 + lj * 16, xa);
        CP_ASYNC16_CA(sAlb + row * 80 + lj * 16, xa + 1024);
        CP_ASYNC16_CG(sBhb + row * 80 + lj * 16, wb);
        CP_ASYNC16_CG(sBlb + row * 80 + lj * 16, wb + 1024);
    }
    CP_COMMIT();

    for (int g = 0; g < NGRP; ++g) {
        const int buf = g & 1;
        if (g + 1 < NGRP) {
            const int kb = (g + 1) * 32;
            const uint32_t off = (uint32_t)((buf ^ 1) * BUFB);
#pragma unroll
            for (int q = 0; q < 2; ++q) {
                int row = lrow + q * 64;
                const __nv_bfloat16* xa = g_xbf + (size_t)(bm0 + row) * KPH + kb + lj * 8;
                const __nv_bfloat16* wb = g_Wbp + (size_t)(bn0 + row) * KPH + kb + lj * 8;
                CP_ASYNC16_CA(sAhb + off + row * 80 + lj * 16, xa);
                CP_ASYNC16_CA(sAlb + off + row * 80 + lj * 16, xa + 1024);
                CP_ASYNC16_CG(sBhb + off + row * 80 + lj * 16, wb);
                CP_ASYNC16_CG(sBlb + off + row * 80 + lj * 16, wb + 1024);
            }
            CP_COMMIT();
            CP_WAIT(1);
        } else {
            CP_WAIT(0);
        }
        __syncthreads();   // group g visible; all warps past group g-1 compute

        const uint32_t off = (uint32_t)(buf * BUFB);
#pragma unroll
        for (int k0 = 0; k0 < 32; k0 += 16) {
            uint32_t ah[4][4], al[4][4], bh[2][4], bl[2][4];
#pragma unroll
            for (int mt = 0; mt < 4; ++mt) {
                uint32_t ro = (uint32_t)(((wm * 64 + mt * 16 + rowoff) * SROW + k0 + kkoff) * 2);
                ldsm_x4(ah[mt][0], ah[mt][1], ah[mt][2], ah[mt][3], sAhb + off + ro);
            }
#pragma unroll
            for (int pt = 0; pt < 2; ++pt) {
                uint32_t ro = (uint32_t)(((wn * 32 + pt * 16 + rowoff) * SROW + k0 + kkoff) * 2);
                ldsm_x4(bh[pt][0], bh[pt][1], bh[pt][2], bh[pt][3], sBhb + off + ro);
            }
            // term 1: A_hi * B_hi
#pragma unroll
            for (int mt = 0; mt < 4; ++mt)
#pragma unroll
                for (int nt = 0; nt < 4; ++nt) {
                    int pt = nt >> 1, hb = nt & 1;
                    mma16816(acc[mt][nt], ah[mt], bh[pt][hb], bh[pt][hb + 2]);
                }
            // term 2: A_lo * B_hi
#pragma unroll
            for (int mt = 0; mt < 4; ++mt) {
                uint32_t ro = (uint32_t)(((wm * 64 + mt * 16 + rowoff) * SROW + k0 + kkoff) * 2);
                ldsm_x4(al[mt][0], al[mt][1], al[mt][2], al[mt][3], sAlb + off + ro);
            }
#pragma unroll
            for (int mt = 0; mt < 4; ++mt)
#pragma unroll
                for (int nt = 0; nt < 4; ++nt) {
                    int pt = nt >> 1, hb = nt & 1;
                    mma16816(acc[mt][nt], al[mt], bh[pt][hb], bh[pt][hb + 2]);
                }
            // term 3: A_hi * B_lo
#pragma unroll
            for (int pt = 0; pt < 2; ++pt) {
                uint32_t ro = (uint32_t)(((wn * 32 + pt * 16 + rowoff) * SROW + k0 + kkoff) * 2);
                ldsm_x4(bl[pt][0], bl[pt][1], bl[pt][2], bl[pt][3], sBlb + off + ro);
            }
#pragma unroll
            for (int mt = 0; mt < 4; ++mt)
#pragma unroll
                for (int nt = 0; nt < 4; ++nt) {
                    int pt = nt >> 1, hb = nt & 1;
                    mma16816(acc[mt][nt], ah[mt], bl[pt][hb], bl[pt][hb + 2]);
                }
        }
        __syncthreads();   // protect this buffer before group g+2's loads
    }

    // epilogue -> xg [cta 256][t][row 64][16 cols(u*4+gate)], bias folded
    const int erow = lane >> 2, ecol = (lane & 3) * 2;
#pragma unroll
    for (int mt = 0; mt < 4; ++mt)
#pragma unroll
        for (int nt = 0; nt < 4; ++nt) {
            int r = bm0 + wm * 64 + mt * 16 + erow;     // m = t*64 + b
            int c = bn0 + wn * 32 + nt * 8 + ecol;
            int tt = r >> 6, b = r & 63;
            int gate = c >> 10, hid = c & 1023, cta = hid >> 2, u = hid & 3;
            size_t base = (size_t)cta * (512 * 64 * 16) + (size_t)tt * 1024 + b * 16 + u * 4 + gate;
            float b0 = g_bsum[c], b1 = g_bsum[c + 1];
            g_xg[base]           = acc[mt][nt][0] + b0;
            g_xg[base + 4]       = acc[mt][nt][1] + b1;   // unit u+1
            g_xg[base + 128]     = acc[mt][nt][2] + b0;   // row b+8
            g_xg[base + 128 + 4] = acc[mt][nt][3] + b1;
        }
}

// ---------------- grid barrier ----------------
__device__ __forceinline__ void grid_sync(unsigned nb)
{
    __threadfence();
    __syncthreads();
    if (threadIdx.x == 0) {
        unsigned gen = *(volatile unsigned*)&g_bar_gen;
        unsigned arr = atomicAdd(&g_bar_cnt, 1);
        if (arr == nb - 1) {
            g_bar_cnt = 0;
            __threadfence();
            *(volatile unsigned*)&g_bar_gen = gen + 1;
        } else {
            while (*(volatile unsigned*)&g_bar_gen == gen) { __nanosleep(32); }
        }
    }
    __syncthreads();
}

// ---------------- HMMA persistent recurrence: __ldg h-fragment loads for L1 cross-CTA reuse ----------------
#define BP       2056
#define REC_BS   (16 * BP * 2)                  // 65792
#define REC_SMEM (REC_BS + 4 * 64 * 16 * 4)     // +16384 = 82176

__global__ __launch_bounds__(256, 2) void lstm_rec_mma(
    const float* __restrict__ Whf, const float* __restrict__ Whi,
    const float* __restrict__ Whg, const float* __restrict__ Who,
    float* __restrict__ out)
{
    extern __shared__ __align__(16) char smr[];
    __nv_bfloat16* Bs = (__nv_bfloat16*)smr;
    float* red = (float*)(smr + REC_BS);     // [ks 4][row 64][col 16]

    const int tid = threadIdx.x, lane = tid & 31, wid = tid >> 5;
    const int cta = blockIdx.x;              // 0..255
    const int mgrp = wid >> 2, ks = wid & 3;
    const unsigned NB = gridDim.x;

    for (int idx = tid; idx < 16 * 1024; idx += 256) {
        int c = idx & 15, k = idx >> 4;
        int u = c >> 2, gate = c & 3;
        const float* W = (gate == 0) ? Whf : (gate == 1) ? Whi : (gate == 2) ? Whg : Who;
        float v = W[(size_t)k * Hdim + cta * 4 + u];
        __nv_bfloat16 hi = __float2bfloat16(v);
        __nv_bfloat16 lo = __float2bfloat16(v - __bfloat162float(hi));
        Bs[c * BP + k]        = hi;
        Bs[c * BP + 1024 + k] = lo;
    }
    g_hF[cta * 256 + tid] = 0u;
    grid_sync(NB);

    const uint32_t Bbase = smem_to_u32(Bs);
    const int rowoff = ((lane >> 3) & 1) * 8 + (lane & 7);
    const int kkoff  = (lane >> 4) * 8;
    const int erow   = lane >> 2;
    const int uu     = (lane & 3) * 2;
    const int crow = tid >> 2, cu = tid & 3;
    const int K    = cta * 4 + cu;
    const size_t ctaSlab = (size_t)cta * (512 * 64 * 16);
    const int pmt = crow >> 4, prr = crow & 15;
    const int c16 = K & 15;
    const int plane = (prr & 7) * 4 + ((c16 >> 1) & 3);
    const int preg  = (prr >> 3) + 2 * (c16 >> 3);
    const int phalf = K & 1;
    const int ktHi = K >> 4, ktLo = 64 + (K >> 4);
    float cst = 0.f;

    const int kt0 = ks * 16;
    const int mtb = mgrp * 2;

    for (int t = 0; t < Tlen; ++t) {
        const uint4* __restrict__ hF4 =
            (const uint4*)(g_hF + (size_t)(t & 1) * 65536);
        float4 xv = *(const float4*)(g_xg + ctaSlab + (size_t)t * 1024 + crow * 16 + cu * 4);

        float acc[2][2][4];
#pragma unroll
        for (int i = 0; i < 2; ++i)
#pragma unroll
            for (int j = 0; j < 2; ++j)
#pragma unroll
                for (int r = 0; r < 4; ++r) acc[i][j][r] = 0.f;

        uint4 ahi[2], alo[2], nhi[2], nlo[2];
#pragma unroll
        for (int mi = 0; mi < 2; ++mi) {
            ahi[mi] = __ldg(hF4 + (kt0 * 4 + mtb + mi) * 32 + lane);
            alo[mi] = __ldg(hF4 + ((kt0 + 64) * 4 + mtb + mi) * 32 + lane);
        }
#pragma unroll 2
        for (int s = 0; s < 16; ++s) {
            const int kt = kt0 + s;
            if (s < 15) {
#pragma unroll
                for (int mi = 0; mi < 2; ++mi) {
                    nhi[mi] = __ldg(hF4 + ((kt + 1) * 4 + mtb + mi) * 32 + lane);
                    nlo[mi] = __ldg(hF4 + ((kt + 65) * 4 + mtb + mi) * 32 + lane);
                }
            }
            uint32_t bh[4], bl[4];
            ldsm_x4(bh[0], bh[1], bh[2], bh[3],
                    Bbase + (uint32_t)((rowoff * BP + kt * 16 + kkoff) * 2));
            ldsm_x4(bl[0], bl[1], bl[2], bl[3],
                    Bbase + (uint32_t)((rowoff * BP + 1024 + kt * 16 + kkoff) * 2));
#pragma unroll
            for (int mi = 0; mi < 2; ++mi) {
                uint32_t ah[4] = {ahi[mi].x, ahi[mi].y, ahi[mi].z, ahi[mi].w};
                uint32_t al[4] = {alo[mi].x, alo[mi].y, alo[mi].z, alo[mi].w};
                mma16816(acc[mi][0], ah, bh[0], bh[2]);
                mma16816(acc[mi][1], ah, bh[1], bh[3]);
                mma16816(acc[mi][0], al, bh[0], bh[2]);
                mma16816(acc[mi][1], al, bh[1], bh[3]);
                mma16816(acc[mi][0], ah, bl[0], bl[2]);
                mma16816(acc[mi][1], ah, bl[1], bl[3]);
            }
#pragma unroll
            for (int mi = 0; mi < 2; ++mi) { ahi[mi] = nhi[mi]; alo[mi] = nlo[mi]; }
        }

#pragma unroll
        for (int mi = 0; mi < 2; ++mi) {
            const int mt = mtb + mi;
#pragma unroll
            for (int nt = 0; nt < 2; ++nt) {
                int base = (ks * 64 + mt * 16 + erow) * 16 + nt * 8 + uu;
                *(float2*)&red[base]       = make_float2(acc[mi][nt][0], acc[mi][nt][1]);
                *(float2*)&red[base + 128] = make_float2(acc[mi][nt][2], acc[mi][nt][3]);
            }
        }
        __syncthreads();
        {
            const float4* r4 = (const float4*)red;
            float4 s0 = r4[(0 * 64 + crow) * 4 + cu];
            float4 s1 = r4[(1 * 64 + crow) * 4 + cu];
            float4 s2 = r4[(2 * 64 + crow) * 4 + cu];
            float4 s3 = r4[(3 * 64 + crow) * 4 + cu];
            float pf = s0.x + s1.x + s2.x + s3.x + xv.x;
            float pi = s0.y + s1.y + s2.y + s3.y + xv.y;
            float pg = s0.z + s1.z + s2.z + s3.z + xv.z;
            float po = s0.w + s1.w + s2.w + s3.w + xv.w;
            float f  = sigf(pf);
            float ii = sigf(pi);
            float gg = tanhf(pg);
            float oo = sigf(po);
            float cn = f * cst + ii * gg;
            cst = cn;
            float hn = tanhf(cn) * oo;
            __nv_bfloat16 hi = __float2bfloat16(hn);
            __nv_bfloat16 lo = __float2bfloat16(hn - __bfloat162float(hi));
            __nv_bfloat16* hw = (__nv_bfloat16*)(g_hF + (size_t)((t + 1) & 1) * 65536);
            hw[(((ktHi * 4 + pmt) * 32 + plane) * 4 + preg) * 2 + phalf] = hi;
            hw[(((ktLo * 4 + pmt) * 32 + plane) * 4 + preg) * 2 + phalf] = lo;
            if (t == Tlen - 1) {
                out[crow * 1024 + K]         = hn;
                out[65536 + crow * 1024 + K] = cn;
            }
        }
        grid_sync(NB);
    }
}

// ---------------- launch ----------------
extern "C" void kernel_launch(void* const* d_in, const int* in_sizes, int n_in,
                              void* d_out, int out_size)
{
    // metadata order = setup_inputs() dict order:
    // 0:x, 1:W_ii, 2:W_hi, 3:W_if, 4:W_hf, 5:W_ig, 6:W_hg, 7:W_io, 8:W_ho,
    // 9:b_ii, 10:b_hi, 11:b_if, 12:b_hf, 13:b_ig, 14:b_hg, 15:b_io, 16:b_ho
    const float* x   = (const float*)d_in[0];
    const float* Wii = (const float*)d_in[1];
    const float* Whi = (const float*)d_in[2];
    const float* Wif = (const float*)d_in[3];
    const float* Whf = (const float*)d_in[4];
    const float* Wig = (const float*)d_in[5];
    const float* Whg = (const float*)d_in[6];
    const float* Wio = (const float*)d_in[7];
    const float* Who = (const float*)d_in[8];
    const float* bii = (const float*)d_in[9];
    const float* bhi = (const float*)d_in[10];
    const float* bif = (const float*)d_in[11];
    const float* bhf = (const float*)d_in[12];
    const float* big = (const float*)d_in[13];
    const float* bhg = (const float*)d_in[14];
    const float* bio = (const float*)d_in[15];
    const float* bho = (const float*)d_in[16];
    float* out = (float*)d_out;

    packW_kernel<<<dim3(16, 16, 4), 256>>>(Wif, Wii, Wig, Wio);
    bias_kernel<<<16, 256>>>(bif, bhf, bii, bhi, big, bhg, bio, bho);
    xconv_kernel<<<Tlen * Bsz, 256>>>(x);
    proj_mma_kernel<<<dim3(G4 / 128, (Tlen * Bsz) / 128), 256>>>();
    cudaFuncSetAttribute(lstm_rec_mma, cudaFuncAttributeMaxDynamicSharedMemorySize, REC_SMEM);
    lstm_rec_mma<<<256, 256, REC_SMEM>>>(Whf, Whi, Whg, Who, out);
}